// round 9
// baseline (speedup 1.0000x reference)
#include <cuda_runtime.h>
#include <cuda_bf16.h>
#include <cstdint>

#define N_NODES 100000
#define H 128
#define F_IN 32
#define F_OUT 16
#define NG 64
#define NEG_SLOPE 0.2f
#define SRC_MAX 2800000   // sum(E) + 4*N self loops

// ---------------- device scratch ----------------
__device__ float g_hA[N_NODES * H];
__device__ float g_hB[N_NODES * H];
__device__ float g_xl[N_NODES * H];
__device__ float g_xr[N_NODES * H];
__device__ int   g_deg[4 * N_NODES];
__device__ int   g_rowptr[4 * N_NODES];
__device__ int   g_cursor[4 * N_NODES];
__device__ int   g_srcs[SRC_MAX];
__device__ int   g_bsum[512];
__device__ float g_pooled[NG * H];
// prepared weights: [4 layers][Wl,Wr] transposed to [n][k] row-major, bf16 hi/lo
__device__ __nv_bfloat16 g_wh[8 * H * H];
__device__ __nv_bfloat16 g_wl[8 * H * H];

// ---------------- mma.sync helpers (sm_80 path, valid on compute_103) ------
__device__ __forceinline__ uint32_t smem_to_u32(const void* p) {
    uint32_t a;
    asm("{ .reg .u64 t; cvta.to.shared.u64 t, %1; cvt.u32.u64 %0, t; }" : "=r"(a) : "l"(p));
    return a;
}
__device__ __forceinline__ void ldsm_x4(uint32_t r[4], uint32_t addr) {
    asm volatile("ldmatrix.sync.aligned.m8n8.x4.shared.b16 {%0,%1,%2,%3}, [%4];"
                 : "=r"(r[0]), "=r"(r[1]), "=r"(r[2]), "=r"(r[3]) : "r"(addr));
}
__device__ __forceinline__ void mma_bf16(float c[4], const uint32_t a[4],
                                         uint32_t b0, uint32_t b1) {
    asm volatile(
        "mma.sync.aligned.m16n8k16.row.col.f32.bf16.bf16.f32 "
        "{%0,%1,%2,%3}, {%4,%5,%6,%7}, {%8,%9}, {%0,%1,%2,%3};"
        : "+f"(c[0]), "+f"(c[1]), "+f"(c[2]), "+f"(c[3])
        : "r"(a[0]), "r"(a[1]), "r"(a[2]), "r"(a[3]), "r"(b0), "r"(b1));
}

// tile row: 256 bytes (128 bf16), XOR-swizzled 16B chunks
__device__ __forceinline__ uint32_t tile_off(int row, int kb) {
    return (uint32_t)(row * 256) + (uint32_t)(kb ^ ((row & 7) << 4));
}

// ---------------- embedding ----------------
__global__ void emb_kernel(const float* __restrict__ x, const float* __restrict__ W,
                           const float* __restrict__ b, float* __restrict__ h) {
    __shared__ float sW[F_IN * H];
    __shared__ float sx[16 * F_IN];
    int tid = threadIdx.x;
    for (int i = tid; i < F_IN * H; i += 128) sW[i] = W[i];
    int n0 = blockIdx.x * 16;
    for (int i = tid; i < 16 * F_IN; i += 128) {
        int r = i >> 5;
        int node = n0 + r;
        sx[i] = (node < N_NODES) ? x[node * F_IN + (i & 31)] : 0.f;
    }
    __syncthreads();
    float bb = b[tid];
    for (int r = 0; r < 16; r++) {
        int node = n0 + r;
        if (node >= N_NODES) break;
        float acc = bb;
#pragma unroll
        for (int k = 0; k < F_IN; k++) acc += sx[r * F_IN + k] * sW[k * H + tid];
        h[node * H + tid] = acc;
    }
}

// ---------------- weight prep: transpose + bf16 hi/lo split ----------------
__global__ void wprep_kernel(const float* __restrict__ Wl, const float* __restrict__ Wr) {
    int idx = blockIdx.x * 256 + threadIdx.x;
    if (idx >= 8 * H * H) return;
    int mat = idx >> 14;            // 0..7 = layer*2 + (0=Wl,1=Wr)
    int e = idx & 16383;
    int n = e >> 7, k = e & 127;
    int layer = mat >> 1;
    const float* W = ((mat & 1) ? Wr : Wl) + layer * H * H;
    float v = W[k * H + n];         // transpose: [n][k] = W[k][n]
    __nv_bfloat16 hi = __float2bfloat16(v);
    float lo = v - __bfloat162float(hi);
    g_wh[idx] = hi;
    g_wl[idx] = __float2bfloat16(lo);
}

// ------- HMMA split-bf16 GEMM: 64-row tile, 2 blk/SM, staged C store -------
#define SMA_HI 0
#define SMA_LO 16384
#define SMW_HI 32768
#define SMW_LO 65536
#define SM_TOTAL 98304

__global__ void __launch_bounds__(256, 2) mma_gemm(
    const float* __restrict__ A,
    const __nv_bfloat16* __restrict__ wlh, const __nv_bfloat16* __restrict__ wll,
    const __nv_bfloat16* __restrict__ wrh, const __nv_bfloat16* __restrict__ wrl,
    float* __restrict__ Cl, float* __restrict__ Cr, int M) {
    extern __shared__ char smem[];
    uint32_t sb = smem_to_u32(smem);
    int tid = threadIdx.x;
    int wid = tid >> 5, lane = tid & 31;
    int row0 = blockIdx.x * 64;

    const __nv_bfloat16* whi = (blockIdx.y == 0) ? wlh : wrh;
    const __nv_bfloat16* wlo = (blockIdx.y == 0) ? wll : wrl;

    // ---- A tile (64 rows): fp32 -> bf16 hi/lo, swizzled ----
    const float4* A4 = (const float4*)(A + (size_t)row0 * H);
#pragma unroll
    for (int it = 0; it < 8; it++) {
        int g = tid + it * 256;
        int row = g >> 5;
        int k4 = g & 31;
        float4 v = make_float4(0.f, 0.f, 0.f, 0.f);
        if (row0 + row < M) v = A4[g];
        __nv_bfloat16 h0 = __float2bfloat16(v.x);
        __nv_bfloat16 h1 = __float2bfloat16(v.y);
        __nv_bfloat16 h2 = __float2bfloat16(v.z);
        __nv_bfloat16 h3 = __float2bfloat16(v.w);
        __nv_bfloat16 l0 = __float2bfloat16(v.x - __bfloat162float(h0));
        __nv_bfloat16 l1 = __float2bfloat16(v.y - __bfloat162float(h1));
        __nv_bfloat16 l2 = __float2bfloat16(v.z - __bfloat162float(h2));
        __nv_bfloat16 l3 = __float2bfloat16(v.w - __bfloat162float(h3));
        uint2 ph, pl;
        ph.x = (uint32_t)__bfloat16_as_ushort(h0) | ((uint32_t)__bfloat16_as_ushort(h1) << 16);
        ph.y = (uint32_t)__bfloat16_as_ushort(h2) | ((uint32_t)__bfloat16_as_ushort(h3) << 16);
        pl.x = (uint32_t)__bfloat16_as_ushort(l0) | ((uint32_t)__bfloat16_as_ushort(l1) << 16);
        pl.y = (uint32_t)__bfloat16_as_ushort(l2) | ((uint32_t)__bfloat16_as_ushort(l3) << 16);
        uint32_t off = tile_off(row, k4 * 8);
        *(uint2*)(smem + SMA_HI + off) = ph;
        *(uint2*)(smem + SMA_LO + off) = pl;
    }
    // ---- W tiles (bf16 [n][k], 128 rows) ----
    const uint2* WH = (const uint2*)whi;
    const uint2* WL = (const uint2*)wlo;
#pragma unroll
    for (int it = 0; it < 16; it++) {
        int g = tid + it * 256;
        int row = g >> 5;
        uint32_t off = tile_off(row, (g & 31) * 8);
        *(uint2*)(smem + SMW_HI + off) = WH[g];
        *(uint2*)(smem + SMW_LO + off) = WL[g];
    }
    __syncthreads();

    int wm = (wid & 1) * 32;
    int wn = (wid >> 1) * 32;

    float acc[2][4][4];
#pragma unroll
    for (int mt = 0; mt < 2; mt++)
#pragma unroll
        for (int nj = 0; nj < 4; nj++)
#pragma unroll
            for (int i = 0; i < 4; i++) acc[mt][nj][i] = 0.f;

    int a_row_off = lane & 15;
    int a_kb_off = (lane >> 4) << 4;
    int b_row_off = (lane & 7) + ((lane >> 4) << 3);
    int b_kb_off = ((lane >> 3) & 1) << 4;

#pragma unroll
    for (int ks = 0; ks < 8; ks++) {
        int kb = ks * 32;
        uint32_t ah[2][4], al[2][4];
#pragma unroll
        for (int mt = 0; mt < 2; mt++) {
            int row = wm + mt * 16 + a_row_off;
            uint32_t off = tile_off(row, kb + a_kb_off);
            ldsm_x4(ah[mt], sb + SMA_HI + off);
            ldsm_x4(al[mt], sb + SMA_LO + off);
        }
        uint32_t bh[2][4], bl[2][4];
#pragma unroll
        for (int ng = 0; ng < 2; ng++) {
            int nrow = wn + ng * 16 + b_row_off;
            uint32_t off = tile_off(nrow, kb + b_kb_off);
            ldsm_x4(bh[ng], sb + SMW_HI + off);
            ldsm_x4(bl[ng], sb + SMW_LO + off);
        }
#pragma unroll
        for (int mt = 0; mt < 2; mt++) {
#pragma unroll
            for (int nj = 0; nj < 4; nj++) {
                int ng = nj >> 1, half = (nj & 1) * 2;
                mma_bf16(acc[mt][nj], ah[mt], bh[ng][half], bh[ng][half + 1]);
                mma_bf16(acc[mt][nj], ah[mt], bl[ng][half], bl[ng][half + 1]);
                mma_bf16(acc[mt][nj], al[mt], bh[ng][half], bh[ng][half + 1]);
            }
        }
    }
    __syncthreads();   // A smem fully consumed -> reuse as C staging

    // ---- stage C in smem (swizzled), then coalesced global store ----
    float* C = (blockIdx.y == 0) ? Cl : Cr;
    float* sC = (float*)smem;   // 64 rows x 128 floats = 32KB (A region)
    int gid = lane >> 2, tig = lane & 3;
#pragma unroll
    for (int mt = 0; mt < 2; mt++) {
#pragma unroll
        for (int nj = 0; nj < 4; nj++) {
            int c = wn + nj * 8 + tig * 2;
            int c4 = c >> 2, half = (c >> 1) & 1;
            int r = wm + mt * 16 + gid;
            int idx0 = r * 128 + ((c4 ^ (r & 31)) << 2) + (half << 1);
            sC[idx0] = acc[mt][nj][0];
            sC[idx0 + 1] = acc[mt][nj][1];
            int r1 = r + 8;
            int idx1 = r1 * 128 + ((c4 ^ (r1 & 31)) << 2) + (half << 1);
            sC[idx1] = acc[mt][nj][2];
            sC[idx1 + 1] = acc[mt][nj][3];
        }
    }
    __syncthreads();
#pragma unroll
    for (int it = 0; it < 8; it++) {
        int f = tid + it * 256;        // float4 index, 2048 total
        int r = f >> 5;
        int c4 = f & 31;
        int sidx = r * 128 + ((c4 ^ (r & 31)) << 2);
        float4 v = *(float4*)&sC[sidx];
        if (row0 + r < M)
            ((float4*)(C + (size_t)(row0 + r) * H))[c4] = v;
    }
}

// ---------------- fused CSR build (all 4 layers) ----------------
__global__ void init_deg_kernel() {
    int i = blockIdx.x * blockDim.x + threadIdx.x;
    if (i < 4 * N_NODES) g_deg[i] = 1;  // self loop
}

__global__ void hist_all_kernel(const int* __restrict__ e0, const int* __restrict__ e1,
                                const int* __restrict__ e2, const int* __restrict__ e3,
                                int E0, int E1, int E2, int E3) {
    int i = blockIdx.x * blockDim.x + threadIdx.x;
    const int* e; int E; int base;
    if (i < E0) { e = e0; E = E0; base = 0; }
    else { i -= E0;
        if (i < E1) { e = e1; E = E1; base = N_NODES; }
        else { i -= E1;
            if (i < E2) { e = e2; E = E2; base = 2 * N_NODES; }
            else { i -= E2; if (i >= E3) return; e = e3; E = E3; base = 3 * N_NODES; } } }
    atomicAdd(&g_deg[base + e[E + i]], 1);
}

__global__ void scan1_kernel() {
    __shared__ int shm[1024];
    int tid = threadIdx.x;
    int i = blockIdx.x * 1024 + tid;
    int v = (i < 4 * N_NODES) ? g_deg[i] : 0;
    shm[tid] = v;
    __syncthreads();
    for (int off = 1; off < 1024; off <<= 1) {
        int t = (tid >= off) ? shm[tid - off] : 0;
        __syncthreads();
        shm[tid] += t;
        __syncthreads();
    }
    if (i < 4 * N_NODES) g_rowptr[i] = shm[tid] - v;
    if (tid == 1023) g_bsum[blockIdx.x] = shm[1023];
}

__global__ void scan2_kernel(int nb) {
    __shared__ int shm[512];
    int tid = threadIdx.x;
    int v = (tid < nb) ? g_bsum[tid] : 0;
    shm[tid] = v;
    __syncthreads();
    for (int off = 1; off < 512; off <<= 1) {
        int t = (tid >= off) ? shm[tid - off] : 0;
        __syncthreads();
        shm[tid] += t;
        __syncthreads();
    }
    if (tid < nb) g_bsum[tid] = shm[tid] - v;
}

__global__ void scan3_kernel() {
    int i = blockIdx.x * blockDim.x + threadIdx.x;
    if (i >= 4 * N_NODES) return;
    int r = g_rowptr[i] + g_bsum[i >> 10];
    g_rowptr[i] = r;
    int layer = i / N_NODES;
    g_srcs[r] = i - layer * N_NODES;  // self loop first
    g_cursor[i] = r + 1;
}

__global__ void scatter_all_kernel(const int* __restrict__ e0, const int* __restrict__ e1,
                                   const int* __restrict__ e2, const int* __restrict__ e3,
                                   int E0, int E1, int E2, int E3) {
    int i = blockIdx.x * blockDim.x + threadIdx.x;
    const int* e; int E; int base;
    if (i < E0) { e = e0; E = E0; base = 0; }
    else { i -= E0;
        if (i < E1) { e = e1; E = E1; base = N_NODES; }
        else { i -= E1;
            if (i < E2) { e = e2; E = E2; base = 2 * N_NODES; }
            else { i -= E2; if (i >= E3) return; e = e3; E = E3; base = 3 * N_NODES; } } }
    int src = e[i];
    int dst = e[E + i];
    int pos = atomicAdd(&g_cursor[base + dst], 1);
    g_srcs[pos] = src;
}

// ---- fused GATv2 softmax-aggregate: warp/dst, dual-stream, depth-2 pipe ---
__global__ void gat_agg_kernel(const float* __restrict__ xl, const float* __restrict__ xr,
                               const float* __restrict__ att, const float* __restrict__ bias,
                               float* __restrict__ hout, int layerBase) {
    int warp = (blockIdx.x * blockDim.x + threadIdx.x) >> 5;
    int lane = threadIdx.x & 31;
    if (warp >= N_NODES) return;
    int v = warp;

    float4 xrv = __ldcs(((const float4*)(xr + (size_t)v * H)) + lane);
    float4 at = ((const float4*)att)[lane];
    float4 bv = ((const float4*)bias)[lane];

    int beg = g_rowptr[layerBase + v];
    int cnt = g_deg[layerBase + v];

    float m0 = -1e30f, s0 = 0.f, a0x = 0.f, a0y = 0.f, a0z = 0.f, a0w = 0.f;
    float m1 = -1e30f, s1 = 0.f, a1x = 0.f, a1y = 0.f, a1z = 0.f, a1w = 0.f;

    // exact-predicated pair loader (uniform branch per warp; no wasted traffic)
#define LOAD_PAIR(p, A, B)                                                        \
    {                                                                             \
        if ((p) < cnt) {                                                          \
            int s_ = __ldcs(&g_srcs[beg + (p)]);                                  \
            A = __ldg((const float4*)(xl + (size_t)s_ * H) + lane);               \
        } else A = make_float4(0.f, 0.f, 0.f, 0.f);                               \
        if ((p) + 1 < cnt) {                                                      \
            int s_ = __ldcs(&g_srcs[beg + (p) + 1]);                              \
            B = __ldg((const float4*)(xl + (size_t)s_ * H) + lane);               \
        } else B = make_float4(0.f, 0.f, 0.f, 0.f);                               \
    }

    float4 a0p, b0p, a1p, b1p, a2p, b2p;
    LOAD_PAIR(0, a0p, b0p);
    LOAD_PAIR(2, a1p, b1p);
    LOAD_PAIR(4, a2p, b2p);

    for (int j = 0; j < cnt; j += 2) {
        float4 pa, pb;
        LOAD_PAIR(j + 6, pa, pb);

        float4 a = a0p, b = b0p;
        bool has1 = (j + 1) < cnt;
        float tx0 = a.x + xrv.x, ty0 = a.y + xrv.y, tz0 = a.z + xrv.z, tw0 = a.w + xrv.w;
        float tx1 = b.x + xrv.x, ty1 = b.y + xrv.y, tz1 = b.z + xrv.z, tw1 = b.w + xrv.w;
        tx0 = fmaxf(tx0, 0.f) + NEG_SLOPE * fminf(tx0, 0.f);
        ty0 = fmaxf(ty0, 0.f) + NEG_SLOPE * fminf(ty0, 0.f);
        tz0 = fmaxf(tz0, 0.f) + NEG_SLOPE * fminf(tz0, 0.f);
        tw0 = fmaxf(tw0, 0.f) + NEG_SLOPE * fminf(tw0, 0.f);
        tx1 = fmaxf(tx1, 0.f) + NEG_SLOPE * fminf(tx1, 0.f);
        ty1 = fmaxf(ty1, 0.f) + NEG_SLOPE * fminf(ty1, 0.f);
        tz1 = fmaxf(tz1, 0.f) + NEG_SLOPE * fminf(tz1, 0.f);
        tw1 = fmaxf(tw1, 0.f) + NEG_SLOPE * fminf(tw1, 0.f);
        float d0 = tx0 * at.x + ty0 * at.y + tz0 * at.z + tw0 * at.w;
        float d1 = tx1 * at.x + ty1 * at.y + tz1 * at.z + tw1 * at.w;
#pragma unroll
        for (int off = 16; off; off >>= 1) {
            d0 += __shfl_xor_sync(0xffffffffu, d0, off);
            d1 += __shfl_xor_sync(0xffffffffu, d1, off);
        }

        {
            float nm = fmaxf(m0, d0);
            float sc = __expf(m0 - nm);
            float ex = __expf(d0 - nm);
            s0 = s0 * sc + ex;
            a0x = a0x * sc + ex * a.x;
            a0y = a0y * sc + ex * a.y;
            a0z = a0z * sc + ex * a.z;
            a0w = a0w * sc + ex * a.w;
            m0 = nm;
        }
        if (has1) {
            float nm = fmaxf(m1, d1);
            float sc = __expf(m1 - nm);
            float ex = __expf(d1 - nm);
            s1 = s1 * sc + ex;
            a1x = a1x * sc + ex * b.x;
            a1y = a1y * sc + ex * b.y;
            a1z = a1z * sc + ex * b.z;
            a1w = a1w * sc + ex * b.w;
            m1 = nm;
        }
        a0p = a1p; b0p = b1p;
        a1p = a2p; b1p = b2p;
        a2p = pa;  b2p = pb;
    }
#undef LOAD_PAIR

    float nm = fmaxf(m0, m1);
    float sc0 = __expf(m0 - nm);
    float sc1 = __expf(m1 - nm);
    float s = s0 * sc0 + s1 * sc1;
    float inv = 1.f / s;
    float4 o;
    o.x = (a0x * sc0 + a1x * sc1) * inv + bv.x;
    o.y = (a0y * sc0 + a1y * sc1) * inv + bv.y;
    o.z = (a0z * sc0 + a1z * sc1) * inv + bv.z;
    o.w = (a0w * sc0 + a1w * sc1) * inv + bv.w;
    __stcs(((float4*)(hout + (size_t)v * H)) + lane, o);
}

// ---------------- pooling + output head ----------------
__global__ void zero_pooled_kernel() {
    int i = blockIdx.x * blockDim.x + threadIdx.x;
    if (i < NG * H) g_pooled[i] = 0.f;
}

__global__ void pool_kernel(const float* __restrict__ h, const int* __restrict__ ground,
                            const int* __restrict__ batch, int ng) {
    __shared__ float acc[NG * H];
    int tid = threadIdx.x;
    for (int i = tid; i < NG * H; i += 128) acc[i] = 0.f;
    __syncthreads();
    for (int g = blockIdx.x; g < ng; g += gridDim.x) {
        int v = ground[g];
        int b = batch[g];
        acc[b * H + tid] += h[(size_t)v * H + tid];
    }
    __syncthreads();
    for (int i = tid; i < NG * H; i += 128) {
        float x = acc[i];
        if (x != 0.f) atomicAdd(&g_pooled[i], x);
    }
}

__global__ void final_kernel(const float* __restrict__ W, const float* __restrict__ b,
                             float* __restrict__ out) {
    int g = blockIdx.x;
    int o = threadIdx.x;
    float acc = b[o];
#pragma unroll
    for (int k = 0; k < H; k++) acc += g_pooled[g * H + k] * W[k * F_OUT + o];
    out[g * F_OUT + o] = acc;
}

// ---------------- launch ----------------
extern "C" void kernel_launch(void* const* d_in, const int* in_sizes, int n_in,
                              void* d_out, int out_size) {
    const float* x      = (const float*)d_in[0];
    const int*   e0     = (const int*)d_in[1];   // edge_index        (layer 0)
    const int*   e2     = (const int*)d_in[2];   // subgraph_edge     (layer 2)
    const int*   e1     = (const int*)d_in[3];   // node_subnode      (layer 1)
    const int*   e3     = (const int*)d_in[4];   // subnode_node      (layer 3)
    const int*   ground = (const int*)d_in[5];
    const int*   batch  = (const int*)d_in[7];
    const float* embW   = (const float*)d_in[8];
    const float* embb   = (const float*)d_in[9];
    const float* Wl     = (const float*)d_in[10];
    const float* Wr     = (const float*)d_in[11];
    const float* att    = (const float*)d_in[12];
    const float* bias   = (const float*)d_in[13];
    const float* outW   = (const float*)d_in[14];
    const float* outb   = (const float*)d_in[15];
    int ng = in_sizes[5];

    int E0 = in_sizes[1] / 2, E1 = in_sizes[3] / 2, E2 = in_sizes[2] / 2, E3 = in_sizes[4] / 2;
    int Etot = E0 + E1 + E2 + E3;

    float *hA, *hB, *xlp, *xrp;
    __nv_bfloat16 *wh, *wl;
    cudaGetSymbolAddress((void**)&hA, g_hA);
    cudaGetSymbolAddress((void**)&hB, g_hB);
    cudaGetSymbolAddress((void**)&xlp, g_xl);
    cudaGetSymbolAddress((void**)&xrp, g_xr);
    cudaGetSymbolAddress((void**)&wh, g_wh);
    cudaGetSymbolAddress((void**)&wl, g_wl);

    cudaFuncSetAttribute(mma_gemm, cudaFuncAttributeMaxDynamicSharedMemorySize, SM_TOTAL);

    emb_kernel<<<(N_NODES + 15) / 16, 128>>>(x, embW, embb, hA);
    wprep_kernel<<<(8 * H * H + 255) / 256, 256>>>(Wl, Wr);
    init_deg_kernel<<<(4 * N_NODES + 255) / 256, 256>>>();

    dim3 ggrid((N_NODES + 63) / 64, 2);
    float* hin = hA;
    float* hout = hB;

    mma_gemm<<<ggrid, 256, SM_TOTAL>>>(hin, wh, wl, wh + H * H, wl + H * H, xlp, xrp, N_NODES);

    int scanBlocks = (4 * N_NODES + 1023) / 1024;
    hist_all_kernel<<<(Etot + 255) / 256, 256>>>(e0, e1, e2, e3, E0, E1, E2, E3);
    scan1_kernel<<<scanBlocks, 1024>>>();
    scan2_kernel<<<1, 512>>>(scanBlocks);
    scan3_kernel<<<(4 * N_NODES + 255) / 256, 256>>>();
    scatter_all_kernel<<<(Etot + 255) / 256, 256>>>(e0, e1, e2, e3, E0, E1, E2, E3);

    for (int l = 0; l < 4; l++) {
        if (l > 0) {
            mma_gemm<<<ggrid, 256, SM_TOTAL>>>(hin, wh + (2 * l) * H * H, wl + (2 * l) * H * H,
                                               wh + (2 * l + 1) * H * H, wl + (2 * l + 1) * H * H,
                                               xlp, xrp, N_NODES);
        }
        gat_agg_kernel<<<(N_NODES * 32 + 255) / 256, 256>>>(
            xlp, xrp, att + l * H, bias + l * H, hout, l * N_NODES);
        float* t = hin; hin = hout; hout = t;
    }

    zero_pooled_kernel<<<(NG * H + 255) / 256, 256>>>();
    pool_kernel<<<640, 128>>>(hin, ground, batch, ng);
    final_kernel<<<NG, F_OUT>>>(outW, outb, (float*)d_out);
}

// round 10
// speedup vs baseline: 1.1822x; 1.1822x over previous
#include <cuda_runtime.h>
#include <cuda_bf16.h>
#include <cstdint>

#define N_NODES 100000
#define H 128
#define F_IN 32
#define F_OUT 16
#define NG 64
#define NEG_SLOPE 0.2f
#define SRC_MAX 2800000   // sum(E) + 4*N self loops

// ---------------- device scratch ----------------
__device__ float g_hA[N_NODES * H];
__device__ float g_hB[N_NODES * H];
__device__ float g_xl[N_NODES * H];
__device__ float g_xr[N_NODES * H];
__device__ int   g_deg[4 * N_NODES];
__device__ int   g_rowptr[4 * N_NODES];
__device__ int   g_cursor[4 * N_NODES];
__device__ int   g_srcs[SRC_MAX];
__device__ int   g_bsum[512];
__device__ float g_pooled[NG * H];
// prepared weights: [4 layers][Wl,Wr] transposed to [n][k] row-major, bf16 hi/lo
__device__ __nv_bfloat16 g_wh[8 * H * H];
__device__ __nv_bfloat16 g_wl[8 * H * H];

// ---------------- mma.sync helpers (sm_80 path, valid on compute_103) ------
__device__ __forceinline__ uint32_t smem_to_u32(const void* p) {
    uint32_t a;
    asm("{ .reg .u64 t; cvta.to.shared.u64 t, %1; cvt.u32.u64 %0, t; }" : "=r"(a) : "l"(p));
    return a;
}
__device__ __forceinline__ void ldsm_x4(uint32_t r[4], uint32_t addr) {
    asm volatile("ldmatrix.sync.aligned.m8n8.x4.shared.b16 {%0,%1,%2,%3}, [%4];"
                 : "=r"(r[0]), "=r"(r[1]), "=r"(r[2]), "=r"(r[3]) : "r"(addr));
}
__device__ __forceinline__ void mma_bf16(float c[4], const uint32_t a[4],
                                         uint32_t b0, uint32_t b1) {
    asm volatile(
        "mma.sync.aligned.m16n8k16.row.col.f32.bf16.bf16.f32 "
        "{%0,%1,%2,%3}, {%4,%5,%6,%7}, {%8,%9}, {%0,%1,%2,%3};"
        : "+f"(c[0]), "+f"(c[1]), "+f"(c[2]), "+f"(c[3])
        : "r"(a[0]), "r"(a[1]), "r"(a[2]), "r"(a[3]), "r"(b0), "r"(b1));
}

// tile row: 256 bytes (128 bf16), XOR-swizzled 16B chunks
__device__ __forceinline__ uint32_t tile_off(int row, int kb) {
    return (uint32_t)(row * 256) + (uint32_t)(kb ^ ((row & 7) << 4));
}

// ---------------- embedding ----------------
__global__ void emb_kernel(const float* __restrict__ x, const float* __restrict__ W,
                           const float* __restrict__ b, float* __restrict__ h) {
    __shared__ float sW[F_IN * H];
    __shared__ float sx[16 * F_IN];
    int tid = threadIdx.x;
    for (int i = tid; i < F_IN * H; i += 128) sW[i] = W[i];
    int n0 = blockIdx.x * 16;
    for (int i = tid; i < 16 * F_IN; i += 128) {
        int r = i >> 5;
        int node = n0 + r;
        sx[i] = (node < N_NODES) ? x[node * F_IN + (i & 31)] : 0.f;
    }
    __syncthreads();
    float bb = b[tid];
    for (int r = 0; r < 16; r++) {
        int node = n0 + r;
        if (node >= N_NODES) break;
        float acc = bb;
#pragma unroll
        for (int k = 0; k < F_IN; k++) acc += sx[r * F_IN + k] * sW[k * H + tid];
        h[node * H + tid] = acc;
    }
}

// ---------------- weight prep: transpose + bf16 hi/lo split ----------------
__global__ void wprep_kernel(const float* __restrict__ Wl, const float* __restrict__ Wr) {
    int idx = blockIdx.x * 256 + threadIdx.x;
    if (idx >= 8 * H * H) return;
    int mat = idx >> 14;            // 0..7 = layer*2 + (0=Wl,1=Wr)
    int e = idx & 16383;
    int n = e >> 7, k = e & 127;
    int layer = mat >> 1;
    const float* W = ((mat & 1) ? Wr : Wl) + layer * H * H;
    float v = W[k * H + n];         // transpose: [n][k] = W[k][n]
    __nv_bfloat16 hi = __float2bfloat16(v);
    float lo = v - __bfloat162float(hi);
    g_wh[idx] = hi;
    g_wl[idx] = __float2bfloat16(lo);
}

// ------- HMMA split-bf16 GEMM: 64-row tile, 8 warps of 32x32, 2 blk/SM -----
// (exact round-7 version: best measured 68.3us)
#define SMA_HI 0
#define SMA_LO 16384
#define SMW_HI 32768
#define SMW_LO 65536
#define SM_TOTAL 98304

__global__ void __launch_bounds__(256, 2) mma_gemm(
    const float* __restrict__ A,
    const __nv_bfloat16* __restrict__ wlh, const __nv_bfloat16* __restrict__ wll,
    const __nv_bfloat16* __restrict__ wrh, const __nv_bfloat16* __restrict__ wrl,
    float* __restrict__ Cl, float* __restrict__ Cr, int M) {
    extern __shared__ char smem[];
    uint32_t sb = smem_to_u32(smem);
    int tid = threadIdx.x;
    int wid = tid >> 5, lane = tid & 31;
    int row0 = blockIdx.x * 64;

    const __nv_bfloat16* whi = (blockIdx.y == 0) ? wlh : wrh;
    const __nv_bfloat16* wlo = (blockIdx.y == 0) ? wll : wrl;

    // ---- A tile (64 rows): fp32 -> bf16 hi/lo, swizzled ----
    const float4* A4 = (const float4*)(A + (size_t)row0 * H);
#pragma unroll
    for (int it = 0; it < 8; it++) {
        int g = tid + it * 256;
        int row = g >> 5;
        int k4 = g & 31;
        float4 v = make_float4(0.f, 0.f, 0.f, 0.f);
        if (row0 + row < M) v = A4[g];
        __nv_bfloat16 h0 = __float2bfloat16(v.x);
        __nv_bfloat16 h1 = __float2bfloat16(v.y);
        __nv_bfloat16 h2 = __float2bfloat16(v.z);
        __nv_bfloat16 h3 = __float2bfloat16(v.w);
        __nv_bfloat16 l0 = __float2bfloat16(v.x - __bfloat162float(h0));
        __nv_bfloat16 l1 = __float2bfloat16(v.y - __bfloat162float(h1));
        __nv_bfloat16 l2 = __float2bfloat16(v.z - __bfloat162float(h2));
        __nv_bfloat16 l3 = __float2bfloat16(v.w - __bfloat162float(h3));
        uint2 ph, pl;
        ph.x = (uint32_t)__bfloat16_as_ushort(h0) | ((uint32_t)__bfloat16_as_ushort(h1) << 16);
        ph.y = (uint32_t)__bfloat16_as_ushort(h2) | ((uint32_t)__bfloat16_as_ushort(h3) << 16);
        pl.x = (uint32_t)__bfloat16_as_ushort(l0) | ((uint32_t)__bfloat16_as_ushort(l1) << 16);
        pl.y = (uint32_t)__bfloat16_as_ushort(l2) | ((uint32_t)__bfloat16_as_ushort(l3) << 16);
        uint32_t off = tile_off(row, k4 * 8);
        *(uint2*)(smem + SMA_HI + off) = ph;
        *(uint2*)(smem + SMA_LO + off) = pl;
    }
    // ---- W tiles (bf16 [n][k], 128 rows) ----
    const uint2* WH = (const uint2*)whi;
    const uint2* WL = (const uint2*)wlo;
#pragma unroll
    for (int it = 0; it < 16; it++) {
        int g = tid + it * 256;
        int row = g >> 5;
        uint32_t off = tile_off(row, (g & 31) * 8);
        *(uint2*)(smem + SMW_HI + off) = WH[g];
        *(uint2*)(smem + SMW_LO + off) = WL[g];
    }
    __syncthreads();

    int wm = (wid & 1) * 32;
    int wn = (wid >> 1) * 32;

    float acc[2][4][4];
#pragma unroll
    for (int mt = 0; mt < 2; mt++)
#pragma unroll
        for (int nj = 0; nj < 4; nj++)
#pragma unroll
            for (int i = 0; i < 4; i++) acc[mt][nj][i] = 0.f;

    int a_row_off = lane & 15;
    int a_kb_off = (lane >> 4) << 4;
    int b_row_off = (lane & 7) + ((lane >> 4) << 3);
    int b_kb_off = ((lane >> 3) & 1) << 4;

#pragma unroll
    for (int ks = 0; ks < 8; ks++) {
        int kb = ks * 32;
        uint32_t ah[2][4], al[2][4];
#pragma unroll
        for (int mt = 0; mt < 2; mt++) {
            int row = wm + mt * 16 + a_row_off;
            uint32_t off = tile_off(row, kb + a_kb_off);
            ldsm_x4(ah[mt], sb + SMA_HI + off);
            ldsm_x4(al[mt], sb + SMA_LO + off);
        }
        uint32_t bh[2][4], bl[2][4];
#pragma unroll
        for (int ng = 0; ng < 2; ng++) {
            int nrow = wn + ng * 16 + b_row_off;
            uint32_t off = tile_off(nrow, kb + b_kb_off);
            ldsm_x4(bh[ng], sb + SMW_HI + off);
            ldsm_x4(bl[ng], sb + SMW_LO + off);
        }
#pragma unroll
        for (int mt = 0; mt < 2; mt++) {
#pragma unroll
            for (int nj = 0; nj < 4; nj++) {
                int ng = nj >> 1, half = (nj & 1) * 2;
                mma_bf16(acc[mt][nj], ah[mt], bh[ng][half], bh[ng][half + 1]);
                mma_bf16(acc[mt][nj], ah[mt], bl[ng][half], bl[ng][half + 1]);
                mma_bf16(acc[mt][nj], al[mt], bh[ng][half], bh[ng][half + 1]);
            }
        }
    }

    float* C = (blockIdx.y == 0) ? Cl : Cr;
    int gid = lane >> 2, tig = lane & 3;
#pragma unroll
    for (int mt = 0; mt < 2; mt++) {
        int r0 = row0 + wm + mt * 16 + gid;
        int r1 = r0 + 8;
#pragma unroll
        for (int nj = 0; nj < 4; nj++) {
            int c = wn + nj * 8 + tig * 2;
            if (r0 < M) *(float2*)(C + (size_t)r0 * H + c) = make_float2(acc[mt][nj][0], acc[mt][nj][1]);
            if (r1 < M) *(float2*)(C + (size_t)r1 * H + c) = make_float2(acc[mt][nj][2], acc[mt][nj][3]);
        }
    }
}

// ---------------- fused CSR build (all 4 layers) ----------------
__global__ void init_deg_kernel() {
    int i = blockIdx.x * blockDim.x + threadIdx.x;
    if (i < 4 * N_NODES) g_deg[i] = 1;  // self loop
}

__global__ void hist_all_kernel(const int* __restrict__ e0, const int* __restrict__ e1,
                                const int* __restrict__ e2, const int* __restrict__ e3,
                                int E0, int E1, int E2, int E3) {
    int i = blockIdx.x * blockDim.x + threadIdx.x;
    const int* e; int E; int base;
    if (i < E0) { e = e0; E = E0; base = 0; }
    else { i -= E0;
        if (i < E1) { e = e1; E = E1; base = N_NODES; }
        else { i -= E1;
            if (i < E2) { e = e2; E = E2; base = 2 * N_NODES; }
            else { i -= E2; if (i >= E3) return; e = e3; E = E3; base = 3 * N_NODES; } } }
    atomicAdd(&g_deg[base + e[E + i]], 1);
}

__global__ void scan1_kernel() {
    __shared__ int shm[1024];
    int tid = threadIdx.x;
    int i = blockIdx.x * 1024 + tid;
    int v = (i < 4 * N_NODES) ? g_deg[i] : 0;
    shm[tid] = v;
    __syncthreads();
    for (int off = 1; off < 1024; off <<= 1) {
        int t = (tid >= off) ? shm[tid - off] : 0;
        __syncthreads();
        shm[tid] += t;
        __syncthreads();
    }
    if (i < 4 * N_NODES) g_rowptr[i] = shm[tid] - v;
    if (tid == 1023) g_bsum[blockIdx.x] = shm[1023];
}

__global__ void scan2_kernel(int nb) {
    __shared__ int shm[512];
    int tid = threadIdx.x;
    int v = (tid < nb) ? g_bsum[tid] : 0;
    shm[tid] = v;
    __syncthreads();
    for (int off = 1; off < 512; off <<= 1) {
        int t = (tid >= off) ? shm[tid - off] : 0;
        __syncthreads();
        shm[tid] += t;
        __syncthreads();
    }
    if (tid < nb) g_bsum[tid] = shm[tid] - v;
}

__global__ void scan3_kernel() {
    int i = blockIdx.x * blockDim.x + threadIdx.x;
    if (i >= 4 * N_NODES) return;
    int r = g_rowptr[i] + g_bsum[i >> 10];
    g_rowptr[i] = r;
    int layer = i / N_NODES;
    g_srcs[r] = i - layer * N_NODES;  // self loop first
    g_cursor[i] = r + 1;
}

__global__ void scatter_all_kernel(const int* __restrict__ e0, const int* __restrict__ e1,
                                   const int* __restrict__ e2, const int* __restrict__ e3,
                                   int E0, int E1, int E2, int E3) {
    int i = blockIdx.x * blockDim.x + threadIdx.x;
    const int* e; int E; int base;
    if (i < E0) { e = e0; E = E0; base = 0; }
    else { i -= E0;
        if (i < E1) { e = e1; E = E1; base = N_NODES; }
        else { i -= E1;
            if (i < E2) { e = e2; E = E2; base = 2 * N_NODES; }
            else { i -= E2; if (i >= E3) return; e = e3; E = E3; base = 3 * N_NODES; } } }
    int src = e[i];
    int dst = e[E + i];
    int pos = atomicAdd(&g_cursor[base + dst], 1);
    g_srcs[pos] = src;
}

// -- fused GATv2 softmax-aggregate: warp/dst, dual-stream, depth-1 prefetch,
//    parity-packed 6-shfl dual reduction (vs 10) --
__global__ void gat_agg_kernel(const float* __restrict__ xl, const float* __restrict__ xr,
                               const float* __restrict__ att, const float* __restrict__ bias,
                               float* __restrict__ hout, int layerBase) {
    int warp = (blockIdx.x * blockDim.x + threadIdx.x) >> 5;
    int lane = threadIdx.x & 31;
    if (warp >= N_NODES) return;
    int v = warp;
    bool odd = lane & 1;

    float4 xrv = __ldcs(((const float4*)(xr + (size_t)v * H)) + lane);
    float4 at = ((const float4*)att)[lane];
    float4 bv = ((const float4*)bias)[lane];

    int beg = g_rowptr[layerBase + v];
    int cnt = g_deg[layerBase + v];

    float m0 = -1e30f, s0 = 0.f, a0x = 0.f, a0y = 0.f, a0z = 0.f, a0w = 0.f;
    float m1 = -1e30f, s1 = 0.f, a1x = 0.f, a1y = 0.f, a1z = 0.f, a1w = 0.f;

    int c0 = __ldg(&g_srcs[beg]);
    int c1 = (cnt > 1) ? __ldg(&g_srcs[beg + 1]) : c0;
    float4 a = __ldg((const float4*)(xl + (size_t)c0 * H) + lane);
    float4 b = __ldg((const float4*)(xl + (size_t)c1 * H) + lane);

    for (int j = 0; j < cnt; j += 2) {
        int n0 = (j + 2 < cnt) ? __ldg(&g_srcs[beg + j + 2]) : c0;
        int n1 = (j + 3 < cnt) ? __ldg(&g_srcs[beg + j + 3]) : n0;
        float4 na = __ldg((const float4*)(xl + (size_t)n0 * H) + lane);
        float4 nb = __ldg((const float4*)(xl + (size_t)n1 * H) + lane);

        bool has1 = (j + 1) < cnt;
        float tx0 = a.x + xrv.x, ty0 = a.y + xrv.y, tz0 = a.z + xrv.z, tw0 = a.w + xrv.w;
        float tx1 = b.x + xrv.x, ty1 = b.y + xrv.y, tz1 = b.z + xrv.z, tw1 = b.w + xrv.w;
        tx0 = fmaxf(tx0, 0.f) + NEG_SLOPE * fminf(tx0, 0.f);
        ty0 = fmaxf(ty0, 0.f) + NEG_SLOPE * fminf(ty0, 0.f);
        tz0 = fmaxf(tz0, 0.f) + NEG_SLOPE * fminf(tz0, 0.f);
        tw0 = fmaxf(tw0, 0.f) + NEG_SLOPE * fminf(tw0, 0.f);
        tx1 = fmaxf(tx1, 0.f) + NEG_SLOPE * fminf(tx1, 0.f);
        ty1 = fmaxf(ty1, 0.f) + NEG_SLOPE * fminf(ty1, 0.f);
        tz1 = fmaxf(tz1, 0.f) + NEG_SLOPE * fminf(tz1, 0.f);
        tw1 = fmaxf(tw1, 0.f) + NEG_SLOPE * fminf(tw1, 0.f);
        float d0 = tx0 * at.x + ty0 * at.y + tz0 * at.z + tw0 * at.w;
        float d1 = tx1 * at.x + ty1 * at.y + tz1 * at.z + tw1 * at.w;

        // parity-packed dual reduction: 6 shfl instead of 10
        // fold: even lanes accumulate edge0, odd lanes edge1
        float send = odd ? d0 : d1;
        float recv = __shfl_xor_sync(0xffffffffu, send, 1);
        float s = odd ? (d1 + recv) : (d0 + recv);
#pragma unroll
        for (int off = 2; off < 32; off <<= 1)
            s += __shfl_xor_sync(0xffffffffu, s, off);
        float t = __shfl_xor_sync(0xffffffffu, s, 1);
        d0 = odd ? t : s;
        d1 = odd ? s : t;

        {
            float nm = fmaxf(m0, d0);
            float sc = __expf(m0 - nm);
            float ex = __expf(d0 - nm);
            s0 = s0 * sc + ex;
            a0x = a0x * sc + ex * a.x;
            a0y = a0y * sc + ex * a.y;
            a0z = a0z * sc + ex * a.z;
            a0w = a0w * sc + ex * a.w;
            m0 = nm;
        }
        if (has1) {
            float nm = fmaxf(m1, d1);
            float sc = __expf(m1 - nm);
            float ex = __expf(d1 - nm);
            s1 = s1 * sc + ex;
            a1x = a1x * sc + ex * b.x;
            a1y = a1y * sc + ex * b.y;
            a1z = a1z * sc + ex * b.z;
            a1w = a1w * sc + ex * b.w;
            m1 = nm;
        }
        a = na; b = nb;
    }

    float nm = fmaxf(m0, m1);
    float sc0 = __expf(m0 - nm);
    float sc1 = __expf(m1 - nm);
    float s = s0 * sc0 + s1 * sc1;
    float inv = 1.f / s;
    float4 o;
    o.x = (a0x * sc0 + a1x * sc1) * inv + bv.x;
    o.y = (a0y * sc0 + a1y * sc1) * inv + bv.y;
    o.z = (a0z * sc0 + a1z * sc1) * inv + bv.z;
    o.w = (a0w * sc0 + a1w * sc1) * inv + bv.w;
    __stcs(((float4*)(hout + (size_t)v * H)) + lane, o);
}

// ---------------- pooling + output head ----------------
__global__ void zero_pooled_kernel() {
    int i = blockIdx.x * blockDim.x + threadIdx.x;
    if (i < NG * H) g_pooled[i] = 0.f;
}

__global__ void pool_kernel(const float* __restrict__ h, const int* __restrict__ ground,
                            const int* __restrict__ batch, int ng) {
    __shared__ float acc[NG * H];
    int tid = threadIdx.x;
    for (int i = tid; i < NG * H; i += 128) acc[i] = 0.f;
    __syncthreads();
    for (int g = blockIdx.x; g < ng; g += gridDim.x) {
        int v = ground[g];
        int b = batch[g];
        acc[b * H + tid] += h[(size_t)v * H + tid];
    }
    __syncthreads();
    for (int i = tid; i < NG * H; i += 128) {
        float x = acc[i];
        if (x != 0.f) atomicAdd(&g_pooled[i], x);
    }
}

__global__ void final_kernel(const float* __restrict__ W, const float* __restrict__ b,
                             float* __restrict__ out) {
    int g = blockIdx.x;
    int o = threadIdx.x;
    float acc = b[o];
#pragma unroll
    for (int k = 0; k < H; k++) acc += g_pooled[g * H + k] * W[k * F_OUT + o];
    out[g * F_OUT + o] = acc;
}

// ---------------- launch ----------------
extern "C" void kernel_launch(void* const* d_in, const int* in_sizes, int n_in,
                              void* d_out, int out_size) {
    const float* x      = (const float*)d_in[0];
    const int*   e0     = (const int*)d_in[1];   // edge_index        (layer 0)
    const int*   e2     = (const int*)d_in[2];   // subgraph_edge     (layer 2)
    const int*   e1     = (const int*)d_in[3];   // node_subnode      (layer 1)
    const int*   e3     = (const int*)d_in[4];   // subnode_node      (layer 3)
    const int*   ground = (const int*)d_in[5];
    const int*   batch  = (const int*)d_in[7];
    const float* embW   = (const float*)d_in[8];
    const float* embb   = (const float*)d_in[9];
    const float* Wl     = (const float*)d_in[10];
    const float* Wr     = (const float*)d_in[11];
    const float* att    = (const float*)d_in[12];
    const float* bias   = (const float*)d_in[13];
    const float* outW   = (const float*)d_in[14];
    const float* outb   = (const float*)d_in[15];
    int ng = in_sizes[5];

    int E0 = in_sizes[1] / 2, E1 = in_sizes[3] / 2, E2 = in_sizes[2] / 2, E3 = in_sizes[4] / 2;
    int Etot = E0 + E1 + E2 + E3;

    float *hA, *hB, *xlp, *xrp;
    __nv_bfloat16 *wh, *wl;
    cudaGetSymbolAddress((void**)&hA, g_hA);
    cudaGetSymbolAddress((void**)&hB, g_hB);
    cudaGetSymbolAddress((void**)&xlp, g_xl);
    cudaGetSymbolAddress((void**)&xrp, g_xr);
    cudaGetSymbolAddress((void**)&wh, g_wh);
    cudaGetSymbolAddress((void**)&wl, g_wl);

    cudaFuncSetAttribute(mma_gemm, cudaFuncAttributeMaxDynamicSharedMemorySize, SM_TOTAL);

    emb_kernel<<<(N_NODES + 15) / 16, 128>>>(x, embW, embb, hA);
    wprep_kernel<<<(8 * H * H + 255) / 256, 256>>>(Wl, Wr);
    init_deg_kernel<<<(4 * N_NODES + 255) / 256, 256>>>();

    dim3 ggrid((N_NODES + 63) / 64, 2);
    float* hin = hA;
    float* hout = hB;

    mma_gemm<<<ggrid, 256, SM_TOTAL>>>(hin, wh, wl, wh + H * H, wl + H * H, xlp, xrp, N_NODES);

    int scanBlocks = (4 * N_NODES + 1023) / 1024;
    hist_all_kernel<<<(Etot + 255) / 256, 256>>>(e0, e1, e2, e3, E0, E1, E2, E3);
    scan1_kernel<<<scanBlocks, 1024>>>();
    scan2_kernel<<<1, 512>>>(scanBlocks);
    scan3_kernel<<<(4 * N_NODES + 255) / 256, 256>>>();
    scatter_all_kernel<<<(Etot + 255) / 256, 256>>>(e0, e1, e2, e3, E0, E1, E2, E3);

    for (int l = 0; l < 4; l++) {
        if (l > 0) {
            mma_gemm<<<ggrid, 256, SM_TOTAL>>>(hin, wh + (2 * l) * H * H, wl + (2 * l) * H * H,
                                               wh + (2 * l + 1) * H * H, wl + (2 * l + 1) * H * H,
                                               xlp, xrp, N_NODES);
        }
        gat_agg_kernel<<<(N_NODES * 32 + 255) / 256, 256>>>(
            xlp, xrp, att + l * H, bias + l * H, hout, l * N_NODES);
        float* t = hin; hin = hout; hout = t;
    }

    zero_pooled_kernel<<<(NG * H + 255) / 256, 256>>>();
    pool_kernel<<<640, 128>>>(hin, ground, batch, ng);
    final_kernel<<<NG, F_OUT>>>(outW, outb, (float*)d_out);
}

// round 11
// speedup vs baseline: 1.1946x; 1.0105x over previous
#include <cuda_runtime.h>
#include <cuda_bf16.h>
#include <cstdint>

#define N_NODES 100000
#define H 128
#define F_IN 32
#define F_OUT 16
#define NG 64
#define NEG_SLOPE 0.2f
#define SRC_MAX 2800000   // sum(E) + 4*N self loops

// ---------------- device scratch ----------------
__device__ float g_hA[N_NODES * H];
__device__ float g_hB[N_NODES * H];
__device__ float g_xl[N_NODES * H];
__device__ float g_xr[N_NODES * H];
__device__ int   g_deg[4 * N_NODES];
__device__ int   g_rowptr[4 * N_NODES];
__device__ int   g_cursor[4 * N_NODES];
__device__ int   g_srcs[SRC_MAX];
__device__ int   g_bsum[512];
__device__ float g_pooled[NG * H];
// prepared weights: [4 layers][Wl,Wr] transposed to [n][k] row-major, bf16 hi/lo
__device__ __nv_bfloat16 g_wh[8 * H * H];
__device__ __nv_bfloat16 g_wl[8 * H * H];

// ---------------- mma.sync helpers (sm_80 path, valid on compute_103) ------
__device__ __forceinline__ uint32_t smem_to_u32(const void* p) {
    uint32_t a;
    asm("{ .reg .u64 t; cvta.to.shared.u64 t, %1; cvt.u32.u64 %0, t; }" : "=r"(a) : "l"(p));
    return a;
}
__device__ __forceinline__ void ldsm_x4(uint32_t r[4], uint32_t addr) {
    asm volatile("ldmatrix.sync.aligned.m8n8.x4.shared.b16 {%0,%1,%2,%3}, [%4];"
                 : "=r"(r[0]), "=r"(r[1]), "=r"(r[2]), "=r"(r[3]) : "r"(addr));
}
__device__ __forceinline__ void mma_bf16(float c[4], const uint32_t a[4],
                                         uint32_t b0, uint32_t b1) {
    asm volatile(
        "mma.sync.aligned.m16n8k16.row.col.f32.bf16.bf16.f32 "
        "{%0,%1,%2,%3}, {%4,%5,%6,%7}, {%8,%9}, {%0,%1,%2,%3};"
        : "+f"(c[0]), "+f"(c[1]), "+f"(c[2]), "+f"(c[3])
        : "r"(a[0]), "r"(a[1]), "r"(a[2]), "r"(a[3]), "r"(b0), "r"(b1));
}

// tile row: 256 bytes (128 bf16), XOR-swizzled 16B chunks
__device__ __forceinline__ uint32_t tile_off(int row, int kb) {
    return (uint32_t)(row * 256) + (uint32_t)(kb ^ ((row & 7) << 4));
}

// ---------------- embedding ----------------
__global__ void emb_kernel(const float* __restrict__ x, const float* __restrict__ W,
                           const float* __restrict__ b, float* __restrict__ h) {
    __shared__ float sW[F_IN * H];
    __shared__ float sx[16 * F_IN];
    int tid = threadIdx.x;
    for (int i = tid; i < F_IN * H; i += 128) sW[i] = W[i];
    int n0 = blockIdx.x * 16;
    for (int i = tid; i < 16 * F_IN; i += 128) {
        int r = i >> 5;
        int node = n0 + r;
        sx[i] = (node < N_NODES) ? x[node * F_IN + (i & 31)] : 0.f;
    }
    __syncthreads();
    float bb = b[tid];
    for (int r = 0; r < 16; r++) {
        int node = n0 + r;
        if (node >= N_NODES) break;
        float acc = bb;
#pragma unroll
        for (int k = 0; k < F_IN; k++) acc += sx[r * F_IN + k] * sW[k * H + tid];
        h[node * H + tid] = acc;
    }
}

// ---------------- weight prep: transpose + bf16 hi/lo split ----------------
__global__ void wprep_kernel(const float* __restrict__ Wl, const float* __restrict__ Wr) {
    int idx = blockIdx.x * 256 + threadIdx.x;
    if (idx >= 8 * H * H) return;
    int mat = idx >> 14;            // 0..7 = layer*2 + (0=Wl,1=Wr)
    int e = idx & 16383;
    int n = e >> 7, k = e & 127;
    int layer = mat >> 1;
    const float* W = ((mat & 1) ? Wr : Wl) + layer * H * H;
    float v = W[k * H + n];         // transpose: [n][k] = W[k][n]
    __nv_bfloat16 hi = __float2bfloat16(v);
    float lo = v - __bfloat162float(hi);
    g_wh[idx] = hi;
    g_wl[idx] = __float2bfloat16(lo);
}

// ------- HMMA split-bf16 GEMM: 64-row tile, 8 warps of 32x32, 2 blk/SM -----
#define SMA_HI 0
#define SMA_LO 16384
#define SMW_HI 32768
#define SMW_LO 65536
#define SM_TOTAL 98304

__global__ void __launch_bounds__(256, 2) mma_gemm(
    const float* __restrict__ A,
    const __nv_bfloat16* __restrict__ wlh, const __nv_bfloat16* __restrict__ wll,
    const __nv_bfloat16* __restrict__ wrh, const __nv_bfloat16* __restrict__ wrl,
    float* __restrict__ Cl, float* __restrict__ Cr, int M) {
    extern __shared__ char smem[];
    uint32_t sb = smem_to_u32(smem);
    int tid = threadIdx.x;
    int wid = tid >> 5, lane = tid & 31;
    int row0 = blockIdx.x * 64;

    const __nv_bfloat16* whi = (blockIdx.y == 0) ? wlh : wrh;
    const __nv_bfloat16* wlo = (blockIdx.y == 0) ? wll : wrl;

    const float4* A4 = (const float4*)(A + (size_t)row0 * H);
#pragma unroll
    for (int it = 0; it < 8; it++) {
        int g = tid + it * 256;
        int row = g >> 5;
        int k4 = g & 31;
        float4 v = make_float4(0.f, 0.f, 0.f, 0.f);
        if (row0 + row < M) v = A4[g];
        __nv_bfloat16 h0 = __float2bfloat16(v.x);
        __nv_bfloat16 h1 = __float2bfloat16(v.y);
        __nv_bfloat16 h2 = __float2bfloat16(v.z);
        __nv_bfloat16 h3 = __float2bfloat16(v.w);
        __nv_bfloat16 l0 = __float2bfloat16(v.x - __bfloat162float(h0));
        __nv_bfloat16 l1 = __float2bfloat16(v.y - __bfloat162float(h1));
        __nv_bfloat16 l2 = __float2bfloat16(v.z - __bfloat162float(h2));
        __nv_bfloat16 l3 = __float2bfloat16(v.w - __bfloat162float(h3));
        uint2 ph, pl;
        ph.x = (uint32_t)__bfloat16_as_ushort(h0) | ((uint32_t)__bfloat16_as_ushort(h1) << 16);
        ph.y = (uint32_t)__bfloat16_as_ushort(h2) | ((uint32_t)__bfloat16_as_ushort(h3) << 16);
        pl.x = (uint32_t)__bfloat16_as_ushort(l0) | ((uint32_t)__bfloat16_as_ushort(l1) << 16);
        pl.y = (uint32_t)__bfloat16_as_ushort(l2) | ((uint32_t)__bfloat16_as_ushort(l3) << 16);
        uint32_t off = tile_off(row, k4 * 8);
        *(uint2*)(smem + SMA_HI + off) = ph;
        *(uint2*)(smem + SMA_LO + off) = pl;
    }
    const uint2* WH = (const uint2*)whi;
    const uint2* WL = (const uint2*)wlo;
#pragma unroll
    for (int it = 0; it < 16; it++) {
        int g = tid + it * 256;
        int row = g >> 5;
        uint32_t off = tile_off(row, (g & 31) * 8);
        *(uint2*)(smem + SMW_HI + off) = WH[g];
        *(uint2*)(smem + SMW_LO + off) = WL[g];
    }
    __syncthreads();

    int wm = (wid & 1) * 32;
    int wn = (wid >> 1) * 32;

    float acc[2][4][4];
#pragma unroll
    for (int mt = 0; mt < 2; mt++)
#pragma unroll
        for (int nj = 0; nj < 4; nj++)
#pragma unroll
            for (int i = 0; i < 4; i++) acc[mt][nj][i] = 0.f;

    int a_row_off = lane & 15;
    int a_kb_off = (lane >> 4) << 4;
    int b_row_off = (lane & 7) + ((lane >> 4) << 3);
    int b_kb_off = ((lane >> 3) & 1) << 4;

#pragma unroll
    for (int ks = 0; ks < 8; ks++) {
        int kb = ks * 32;
        uint32_t ah[2][4], al[2][4];
#pragma unroll
        for (int mt = 0; mt < 2; mt++) {
            int row = wm + mt * 16 + a_row_off;
            uint32_t off = tile_off(row, kb + a_kb_off);
            ldsm_x4(ah[mt], sb + SMA_HI + off);
            ldsm_x4(al[mt], sb + SMA_LO + off);
        }
        uint32_t bh[2][4], bl[2][4];
#pragma unroll
        for (int ng = 0; ng < 2; ng++) {
            int nrow = wn + ng * 16 + b_row_off;
            uint32_t off = tile_off(nrow, kb + b_kb_off);
            ldsm_x4(bh[ng], sb + SMW_HI + off);
            ldsm_x4(bl[ng], sb + SMW_LO + off);
        }
#pragma unroll
        for (int mt = 0; mt < 2; mt++) {
#pragma unroll
            for (int nj = 0; nj < 4; nj++) {
                int ng = nj >> 1, half = (nj & 1) * 2;
                mma_bf16(acc[mt][nj], ah[mt], bh[ng][half], bh[ng][half + 1]);
                mma_bf16(acc[mt][nj], ah[mt], bl[ng][half], bl[ng][half + 1]);
                mma_bf16(acc[mt][nj], al[mt], bh[ng][half], bh[ng][half + 1]);
            }
        }
    }

    float* C = (blockIdx.y == 0) ? Cl : Cr;
    int gid = lane >> 2, tig = lane & 3;
#pragma unroll
    for (int mt = 0; mt < 2; mt++) {
        int r0 = row0 + wm + mt * 16 + gid;
        int r1 = r0 + 8;
#pragma unroll
        for (int nj = 0; nj < 4; nj++) {
            int c = wn + nj * 8 + tig * 2;
            if (r0 < M) *(float2*)(C + (size_t)r0 * H + c) = make_float2(acc[mt][nj][0], acc[mt][nj][1]);
            if (r1 < M) *(float2*)(C + (size_t)r1 * H + c) = make_float2(acc[mt][nj][2], acc[mt][nj][3]);
        }
    }
}

// ---------------- fused CSR build (all 4 layers) ----------------
__global__ void init_deg_kernel() {
    int i = blockIdx.x * blockDim.x + threadIdx.x;
    if (i < 4 * N_NODES) g_deg[i] = 1;  // self loop
}

__global__ void hist_all_kernel(const int* __restrict__ e0, const int* __restrict__ e1,
                                const int* __restrict__ e2, const int* __restrict__ e3,
                                int E0, int E1, int E2, int E3) {
    int i = blockIdx.x * blockDim.x + threadIdx.x;
    const int* e; int E; int base;
    if (i < E0) { e = e0; E = E0; base = 0; }
    else { i -= E0;
        if (i < E1) { e = e1; E = E1; base = N_NODES; }
        else { i -= E1;
            if (i < E2) { e = e2; E = E2; base = 2 * N_NODES; }
            else { i -= E2; if (i >= E3) return; e = e3; E = E3; base = 3 * N_NODES; } } }
    atomicAdd(&g_deg[base + e[E + i]], 1);
}

__global__ void scan1_kernel() {
    __shared__ int shm[1024];
    int tid = threadIdx.x;
    int i = blockIdx.x * 1024 + tid;
    int v = (i < 4 * N_NODES) ? g_deg[i] : 0;
    shm[tid] = v;
    __syncthreads();
    for (int off = 1; off < 1024; off <<= 1) {
        int t = (tid >= off) ? shm[tid - off] : 0;
        __syncthreads();
        shm[tid] += t;
        __syncthreads();
    }
    if (i < 4 * N_NODES) g_rowptr[i] = shm[tid] - v;
    if (tid == 1023) g_bsum[blockIdx.x] = shm[1023];
}

__global__ void scan2_kernel(int nb) {
    __shared__ int shm[512];
    int tid = threadIdx.x;
    int v = (tid < nb) ? g_bsum[tid] : 0;
    shm[tid] = v;
    __syncthreads();
    for (int off = 1; off < 512; off <<= 1) {
        int t = (tid >= off) ? shm[tid - off] : 0;
        __syncthreads();
        shm[tid] += t;
        __syncthreads();
    }
    if (tid < nb) g_bsum[tid] = shm[tid] - v;
}

__global__ void scan3_kernel() {
    int i = blockIdx.x * blockDim.x + threadIdx.x;
    if (i >= 4 * N_NODES) return;
    int r = g_rowptr[i] + g_bsum[i >> 10];
    g_rowptr[i] = r;
    int layer = i / N_NODES;
    g_srcs[r] = i - layer * N_NODES;  // self loop first
    g_cursor[i] = r + 1;
}

__global__ void scatter_all_kernel(const int* __restrict__ e0, const int* __restrict__ e1,
                                   const int* __restrict__ e2, const int* __restrict__ e3,
                                   int E0, int E1, int E2, int E3) {
    int i = blockIdx.x * blockDim.x + threadIdx.x;
    const int* e; int E; int base;
    if (i < E0) { e = e0; E = E0; base = 0; }
    else { i -= E0;
        if (i < E1) { e = e1; E = E1; base = N_NODES; }
        else { i -= E1;
            if (i < E2) { e = e2; E = E2; base = 2 * N_NODES; }
            else { i -= E2; if (i >= E3) return; e = e3; E = E3; base = 3 * N_NODES; } } }
    int src = e[i];
    int dst = e[E + i];
    int pos = atomicAdd(&g_cursor[base + dst], 1);
    g_srcs[pos] = src;
}

// -- fused GATv2 softmax-aggregate: warp/dst, dual-stream, depth-1 prefetch,
//    parity-packed 6-shfl dual reduction --
__global__ void gat_agg_kernel(const float* __restrict__ xl, const float* __restrict__ xr,
                               const float* __restrict__ att, const float* __restrict__ bias,
                               float* __restrict__ hout, int layerBase) {
    int warp = (blockIdx.x * blockDim.x + threadIdx.x) >> 5;
    int lane = threadIdx.x & 31;
    if (warp >= N_NODES) return;
    int v = warp;
    bool odd = lane & 1;

    float4 xrv = __ldcs(((const float4*)(xr + (size_t)v * H)) + lane);
    float4 at = ((const float4*)att)[lane];
    float4 bv = ((const float4*)bias)[lane];

    int beg = g_rowptr[layerBase + v];
    int cnt = g_deg[layerBase + v];

    float m0 = -1e30f, s0 = 0.f, a0x = 0.f, a0y = 0.f, a0z = 0.f, a0w = 0.f;
    float m1 = -1e30f, s1 = 0.f, a1x = 0.f, a1y = 0.f, a1z = 0.f, a1w = 0.f;

    int c0 = __ldg(&g_srcs[beg]);
    int c1 = (cnt > 1) ? __ldg(&g_srcs[beg + 1]) : c0;
    float4 a = __ldg((const float4*)(xl + (size_t)c0 * H) + lane);
    float4 b = __ldg((const float4*)(xl + (size_t)c1 * H) + lane);

    for (int j = 0; j < cnt; j += 2) {
        int n0 = (j + 2 < cnt) ? __ldg(&g_srcs[beg + j + 2]) : c0;
        int n1 = (j + 3 < cnt) ? __ldg(&g_srcs[beg + j + 3]) : n0;
        float4 na = __ldg((const float4*)(xl + (size_t)n0 * H) + lane);
        float4 nb = __ldg((const float4*)(xl + (size_t)n1 * H) + lane);

        bool has1 = (j + 1) < cnt;
        float tx0 = a.x + xrv.x, ty0 = a.y + xrv.y, tz0 = a.z + xrv.z, tw0 = a.w + xrv.w;
        float tx1 = b.x + xrv.x, ty1 = b.y + xrv.y, tz1 = b.z + xrv.z, tw1 = b.w + xrv.w;
        tx0 = fmaxf(tx0, 0.f) + NEG_SLOPE * fminf(tx0, 0.f);
        ty0 = fmaxf(ty0, 0.f) + NEG_SLOPE * fminf(ty0, 0.f);
        tz0 = fmaxf(tz0, 0.f) + NEG_SLOPE * fminf(tz0, 0.f);
        tw0 = fmaxf(tw0, 0.f) + NEG_SLOPE * fminf(tw0, 0.f);
        tx1 = fmaxf(tx1, 0.f) + NEG_SLOPE * fminf(tx1, 0.f);
        ty1 = fmaxf(ty1, 0.f) + NEG_SLOPE * fminf(ty1, 0.f);
        tz1 = fmaxf(tz1, 0.f) + NEG_SLOPE * fminf(tz1, 0.f);
        tw1 = fmaxf(tw1, 0.f) + NEG_SLOPE * fminf(tw1, 0.f);
        float d0 = tx0 * at.x + ty0 * at.y + tz0 * at.z + tw0 * at.w;
        float d1 = tx1 * at.x + ty1 * at.y + tz1 * at.z + tw1 * at.w;

        float send = odd ? d0 : d1;
        float recv = __shfl_xor_sync(0xffffffffu, send, 1);
        float s = odd ? (d1 + recv) : (d0 + recv);
#pragma unroll
        for (int off = 2; off < 32; off <<= 1)
            s += __shfl_xor_sync(0xffffffffu, s, off);
        float t = __shfl_xor_sync(0xffffffffu, s, 1);
        d0 = odd ? t : s;
        d1 = odd ? s : t;

        {
            float nm = fmaxf(m0, d0);
            float sc = __expf(m0 - nm);
            float ex = __expf(d0 - nm);
            s0 = s0 * sc + ex;
            a0x = a0x * sc + ex * a.x;
            a0y = a0y * sc + ex * a.y;
            a0z = a0z * sc + ex * a.z;
            a0w = a0w * sc + ex * a.w;
            m0 = nm;
        }
        if (has1) {
            float nm = fmaxf(m1, d1);
            float sc = __expf(m1 - nm);
            float ex = __expf(d1 - nm);
            s1 = s1 * sc + ex;
            a1x = a1x * sc + ex * b.x;
            a1y = a1y * sc + ex * b.y;
            a1z = a1z * sc + ex * b.z;
            a1w = a1w * sc + ex * b.w;
            m1 = nm;
        }
        a = na; b = nb;
    }

    float nm = fmaxf(m0, m1);
    float sc0 = __expf(m0 - nm);
    float sc1 = __expf(m1 - nm);
    float s = s0 * sc0 + s1 * sc1;
    float inv = 1.f / s;
    float4 o;
    o.x = (a0x * sc0 + a1x * sc1) * inv + bv.x;
    o.y = (a0y * sc0 + a1y * sc1) * inv + bv.y;
    o.z = (a0z * sc0 + a1z * sc1) * inv + bv.z;
    o.w = (a0w * sc0 + a1w * sc1) * inv + bv.w;
    __stcs(((float4*)(hout + (size_t)v * H)) + lane, o);
}

// ---------------- pooling + output head ----------------
__global__ void zero_pooled_kernel() {
    int i = blockIdx.x * blockDim.x + threadIdx.x;
    if (i < NG * H) g_pooled[i] = 0.f;
}

__global__ void pool_kernel(const float* __restrict__ h, const int* __restrict__ ground,
                            const int* __restrict__ batch, int ng) {
    __shared__ float acc[NG * H];
    int tid = threadIdx.x;
    for (int i = tid; i < NG * H; i += 128) acc[i] = 0.f;
    __syncthreads();
    for (int g = blockIdx.x; g < ng; g += gridDim.x) {
        int v = ground[g];
        int b = batch[g];
        acc[b * H + tid] += h[(size_t)v * H + tid];
    }
    __syncthreads();
    for (int i = tid; i < NG * H; i += 128) {
        float x = acc[i];
        if (x != 0.f) atomicAdd(&g_pooled[i], x);
    }
}

__global__ void final_kernel(const float* __restrict__ W, const float* __restrict__ b,
                             float* __restrict__ out) {
    int g = blockIdx.x;
    int o = threadIdx.x;
    float acc = b[o];
#pragma unroll
    for (int k = 0; k < H; k++) acc += g_pooled[g * H + k] * W[k * F_OUT + o];
    out[g * F_OUT + o] = acc;
}

// ---------------- launch ----------------
extern "C" void kernel_launch(void* const* d_in, const int* in_sizes, int n_in,
                              void* d_out, int out_size) {
    const float* x      = (const float*)d_in[0];
    const int*   e0     = (const int*)d_in[1];   // edge_index        (layer 0)
    const int*   e2     = (const int*)d_in[2];   // subgraph_edge     (layer 2)
    const int*   e1     = (const int*)d_in[3];   // node_subnode      (layer 1)
    const int*   e3     = (const int*)d_in[4];   // subnode_node      (layer 3)
    const int*   ground = (const int*)d_in[5];
    const int*   batch  = (const int*)d_in[7];
    const float* embW   = (const float*)d_in[8];
    const float* embb   = (const float*)d_in[9];
    const float* Wl     = (const float*)d_in[10];
    const float* Wr     = (const float*)d_in[11];
    const float* att    = (const float*)d_in[12];
    const float* bias   = (const float*)d_in[13];
    const float* outW   = (const float*)d_in[14];
    const float* outb   = (const float*)d_in[15];
    int ng = in_sizes[5];

    int E0 = in_sizes[1] / 2, E1 = in_sizes[3] / 2, E2 = in_sizes[2] / 2, E3 = in_sizes[4] / 2;
    int Etot = E0 + E1 + E2 + E3;

    float *hA, *hB, *xlp, *xrp;
    __nv_bfloat16 *wh, *wl;
    cudaGetSymbolAddress((void**)&hA, g_hA);
    cudaGetSymbolAddress((void**)&hB, g_hB);
    cudaGetSymbolAddress((void**)&xlp, g_xl);
    cudaGetSymbolAddress((void**)&xrp, g_xr);
    cudaGetSymbolAddress((void**)&wh, g_wh);
    cudaGetSymbolAddress((void**)&wl, g_wl);

    cudaFuncSetAttribute(mma_gemm, cudaFuncAttributeMaxDynamicSharedMemorySize, SM_TOTAL);

    // lazy one-time host objects (created on the uncaptured correctness call)
    static cudaStream_t s2 = nullptr;
    static cudaEvent_t evFork = nullptr, evJoin = nullptr;
    if (!s2) {
        cudaStreamCreateWithFlags(&s2, cudaStreamNonBlocking);
        cudaEventCreateWithFlags(&evFork, cudaEventDisableTiming);
        cudaEventCreateWithFlags(&evJoin, cudaEventDisableTiming);
    }

    // ---- fork: CSR build chain on side stream, independent of emb/gemm ----
    cudaEventRecord(evFork, 0);
    cudaStreamWaitEvent(s2, evFork, 0);

    int scanBlocks = (4 * N_NODES + 1023) / 1024;
    init_deg_kernel<<<(4 * N_NODES + 255) / 256, 256, 0, s2>>>();
    hist_all_kernel<<<(Etot + 255) / 256, 256, 0, s2>>>(e0, e1, e2, e3, E0, E1, E2, E3);
    scan1_kernel<<<scanBlocks, 1024, 0, s2>>>();
    scan2_kernel<<<1, 512, 0, s2>>>(scanBlocks);
    scan3_kernel<<<(4 * N_NODES + 255) / 256, 256, 0, s2>>>();
    scatter_all_kernel<<<(Etot + 255) / 256, 256, 0, s2>>>(e0, e1, e2, e3, E0, E1, E2, E3);
    zero_pooled_kernel<<<(NG * H + 255) / 256, 256, 0, s2>>>();
    cudaEventRecord(evJoin, s2);

    // ---- main stream: emb -> wprep -> gemm0 (overlaps CSR chain) ----
    emb_kernel<<<(N_NODES + 15) / 16, 128>>>(x, embW, embb, hA);
    wprep_kernel<<<(8 * H * H + 255) / 256, 256>>>(Wl, Wr);

    dim3 ggrid((N_NODES + 63) / 64, 2);
    float* hin = hA;
    float* hout = hB;

    mma_gemm<<<ggrid, 256, SM_TOTAL>>>(hin, wh, wl, wh + H * H, wl + H * H, xlp, xrp, N_NODES);

    // ---- join: first agg needs the CSR ----
    cudaStreamWaitEvent(0, evJoin, 0);

    for (int l = 0; l < 4; l++) {
        if (l > 0) {
            mma_gemm<<<ggrid, 256, SM_TOTAL>>>(hin, wh + (2 * l) * H * H, wl + (2 * l) * H * H,
                                               wh + (2 * l + 1) * H * H, wl + (2 * l + 1) * H * H,
                                               xlp, xrp, N_NODES);
        }
        gat_agg_kernel<<<(N_NODES * 32 + 255) / 256, 256>>>(
            xlp, xrp, att + l * H, bias + l * H, hout, l * N_NODES);
        float* t = hin; hin = hout; hout = t;
    }

    pool_kernel<<<640, 128>>>(hin, ground, batch, ng);
    final_kernel<<<NG, F_OUT>>>(outW, outb, (float*)d_out);
}

// round 12
// speedup vs baseline: 1.1969x; 1.0019x over previous
#include <cuda_runtime.h>
#include <cuda_bf16.h>
#include <cstdint>

#define N_NODES 100000
#define H 128
#define F_IN 32
#define F_OUT 16
#define NG 64
#define NEG_SLOPE 0.2f
#define SRC_MAX 2800000   // sum(E) + 4*N self loops
#define CHUNK 50048       // = 782*64, agg/gemm pipeline split point

// ---------------- device scratch ----------------
__device__ float g_hA[N_NODES * H];
__device__ float g_hB[N_NODES * H];
__device__ float g_xlA[N_NODES * H];
__device__ float g_xrA[N_NODES * H];
__device__ float g_xlB[N_NODES * H];
__device__ float g_xrB[N_NODES * H];
__device__ int   g_deg[4 * N_NODES];
__device__ int   g_rowptr[4 * N_NODES];
__device__ int   g_cursor[4 * N_NODES];
__device__ int   g_srcs[SRC_MAX];
__device__ int   g_bsum[512];
__device__ float g_pooled[NG * H];
// prepared weights: [4 layers][Wl,Wr] transposed to [n][k] row-major, bf16 hi/lo
__device__ __nv_bfloat16 g_wh[8 * H * H];
__device__ __nv_bfloat16 g_wl[8 * H * H];

// ---------------- mma.sync helpers (sm_80 path, valid on compute_103) ------
__device__ __forceinline__ uint32_t smem_to_u32(const void* p) {
    uint32_t a;
    asm("{ .reg .u64 t; cvta.to.shared.u64 t, %1; cvt.u32.u64 %0, t; }" : "=r"(a) : "l"(p));
    return a;
}
__device__ __forceinline__ void ldsm_x4(uint32_t r[4], uint32_t addr) {
    asm volatile("ldmatrix.sync.aligned.m8n8.x4.shared.b16 {%0,%1,%2,%3}, [%4];"
                 : "=r"(r[0]), "=r"(r[1]), "=r"(r[2]), "=r"(r[3]) : "r"(addr));
}
__device__ __forceinline__ void mma_bf16(float c[4], const uint32_t a[4],
                                         uint32_t b0, uint32_t b1) {
    asm volatile(
        "mma.sync.aligned.m16n8k16.row.col.f32.bf16.bf16.f32 "
        "{%0,%1,%2,%3}, {%4,%5,%6,%7}, {%8,%9}, {%0,%1,%2,%3};"
        : "+f"(c[0]), "+f"(c[1]), "+f"(c[2]), "+f"(c[3])
        : "r"(a[0]), "r"(a[1]), "r"(a[2]), "r"(a[3]), "r"(b0), "r"(b1));
}

// tile row: 256 bytes (128 bf16), XOR-swizzled 16B chunks
__device__ __forceinline__ uint32_t tile_off(int row, int kb) {
    return (uint32_t)(row * 256) + (uint32_t)(kb ^ ((row & 7) << 4));
}

// ---------------- embedding ----------------
__global__ void emb_kernel(const float* __restrict__ x, const float* __restrict__ W,
                           const float* __restrict__ b, float* __restrict__ h) {
    __shared__ float sW[F_IN * H];
    __shared__ float sx[16 * F_IN];
    int tid = threadIdx.x;
    for (int i = tid; i < F_IN * H; i += 128) sW[i] = W[i];
    int n0 = blockIdx.x * 16;
    for (int i = tid; i < 16 * F_IN; i += 128) {
        int r = i >> 5;
        int node = n0 + r;
        sx[i] = (node < N_NODES) ? x[node * F_IN + (i & 31)] : 0.f;
    }
    __syncthreads();
    float bb = b[tid];
    for (int r = 0; r < 16; r++) {
        int node = n0 + r;
        if (node >= N_NODES) break;
        float acc = bb;
#pragma unroll
        for (int k = 0; k < F_IN; k++) acc += sx[r * F_IN + k] * sW[k * H + tid];
        h[node * H + tid] = acc;
    }
}

// ---------------- weight prep: transpose + bf16 hi/lo split ----------------
__global__ void wprep_kernel(const float* __restrict__ Wl, const float* __restrict__ Wr) {
    int idx = blockIdx.x * 256 + threadIdx.x;
    if (idx >= 8 * H * H) return;
    int mat = idx >> 14;            // 0..7 = layer*2 + (0=Wl,1=Wr)
    int e = idx & 16383;
    int n = e >> 7, k = e & 127;
    int layer = mat >> 1;
    const float* W = ((mat & 1) ? Wr : Wl) + layer * H * H;
    float v = W[k * H + n];         // transpose: [n][k] = W[k][n]
    __nv_bfloat16 hi = __float2bfloat16(v);
    float lo = v - __bfloat162float(hi);
    g_wh[idx] = hi;
    g_wl[idx] = __float2bfloat16(lo);
}

// ------- HMMA split-bf16 GEMM: 64-row tile, 8 warps of 32x32, 2 blk/SM -----
#define SMA_HI 0
#define SMA_LO 16384
#define SMW_HI 32768
#define SMW_LO 65536
#define SM_TOTAL 98304

__global__ void __launch_bounds__(256, 2) mma_gemm(
    const float* __restrict__ A,
    const __nv_bfloat16* __restrict__ wlh, const __nv_bfloat16* __restrict__ wll,
    const __nv_bfloat16* __restrict__ wrh, const __nv_bfloat16* __restrict__ wrl,
    float* __restrict__ Cl, float* __restrict__ Cr, int M, int rowBase) {
    extern __shared__ char smem[];
    uint32_t sb = smem_to_u32(smem);
    int tid = threadIdx.x;
    int wid = tid >> 5, lane = tid & 31;
    int row0 = rowBase + blockIdx.x * 64;

    const __nv_bfloat16* whi = (blockIdx.y == 0) ? wlh : wrh;
    const __nv_bfloat16* wlo = (blockIdx.y == 0) ? wll : wrl;

    const float4* A4 = (const float4*)(A + (size_t)row0 * H);
#pragma unroll
    for (int it = 0; it < 8; it++) {
        int g = tid + it * 256;
        int row = g >> 5;
        int k4 = g & 31;
        float4 v = make_float4(0.f, 0.f, 0.f, 0.f);
        if (row0 + row < M) v = A4[g];
        __nv_bfloat16 h0 = __float2bfloat16(v.x);
        __nv_bfloat16 h1 = __float2bfloat16(v.y);
        __nv_bfloat16 h2 = __float2bfloat16(v.z);
        __nv_bfloat16 h3 = __float2bfloat16(v.w);
        __nv_bfloat16 l0 = __float2bfloat16(v.x - __bfloat162float(h0));
        __nv_bfloat16 l1 = __float2bfloat16(v.y - __bfloat162float(h1));
        __nv_bfloat16 l2 = __float2bfloat16(v.z - __bfloat162float(h2));
        __nv_bfloat16 l3 = __float2bfloat16(v.w - __bfloat162float(h3));
        uint2 ph, pl;
        ph.x = (uint32_t)__bfloat16_as_ushort(h0) | ((uint32_t)__bfloat16_as_ushort(h1) << 16);
        ph.y = (uint32_t)__bfloat16_as_ushort(h2) | ((uint32_t)__bfloat16_as_ushort(h3) << 16);
        pl.x = (uint32_t)__bfloat16_as_ushort(l0) | ((uint32_t)__bfloat16_as_ushort(l1) << 16);
        pl.y = (uint32_t)__bfloat16_as_ushort(l2) | ((uint32_t)__bfloat16_as_ushort(l3) << 16);
        uint32_t off = tile_off(row, k4 * 8);
        *(uint2*)(smem + SMA_HI + off) = ph;
        *(uint2*)(smem + SMA_LO + off) = pl;
    }
    const uint2* WH = (const uint2*)whi;
    const uint2* WL = (const uint2*)wlo;
#pragma unroll
    for (int it = 0; it < 16; it++) {
        int g = tid + it * 256;
        int row = g >> 5;
        uint32_t off = tile_off(row, (g & 31) * 8);
        *(uint2*)(smem + SMW_HI + off) = WH[g];
        *(uint2*)(smem + SMW_LO + off) = WL[g];
    }
    __syncthreads();

    int wm = (wid & 1) * 32;
    int wn = (wid >> 1) * 32;

    float acc[2][4][4];
#pragma unroll
    for (int mt = 0; mt < 2; mt++)
#pragma unroll
        for (int nj = 0; nj < 4; nj++)
#pragma unroll
            for (int i = 0; i < 4; i++) acc[mt][nj][i] = 0.f;

    int a_row_off = lane & 15;
    int a_kb_off = (lane >> 4) << 4;
    int b_row_off = (lane & 7) + ((lane >> 4) << 3);
    int b_kb_off = ((lane >> 3) & 1) << 4;

#pragma unroll
    for (int ks = 0; ks < 8; ks++) {
        int kb = ks * 32;
        uint32_t ah[2][4], al[2][4];
#pragma unroll
        for (int mt = 0; mt < 2; mt++) {
            int row = wm + mt * 16 + a_row_off;
            uint32_t off = tile_off(row, kb + a_kb_off);
            ldsm_x4(ah[mt], sb + SMA_HI + off);
            ldsm_x4(al[mt], sb + SMA_LO + off);
        }
        uint32_t bh[2][4], bl[2][4];
#pragma unroll
        for (int ng = 0; ng < 2; ng++) {
            int nrow = wn + ng * 16 + b_row_off;
            uint32_t off = tile_off(nrow, kb + b_kb_off);
            ldsm_x4(bh[ng], sb + SMW_HI + off);
            ldsm_x4(bl[ng], sb + SMW_LO + off);
        }
#pragma unroll
        for (int mt = 0; mt < 2; mt++) {
#pragma unroll
            for (int nj = 0; nj < 4; nj++) {
                int ng = nj >> 1, half = (nj & 1) * 2;
                mma_bf16(acc[mt][nj], ah[mt], bh[ng][half], bh[ng][half + 1]);
                mma_bf16(acc[mt][nj], ah[mt], bl[ng][half], bl[ng][half + 1]);
                mma_bf16(acc[mt][nj], al[mt], bh[ng][half], bh[ng][half + 1]);
            }
        }
    }

    float* C = (blockIdx.y == 0) ? Cl : Cr;
    int gid = lane >> 2, tig = lane & 3;
#pragma unroll
    for (int mt = 0; mt < 2; mt++) {
        int r0 = row0 + wm + mt * 16 + gid;
        int r1 = r0 + 8;
#pragma unroll
        for (int nj = 0; nj < 4; nj++) {
            int c = wn + nj * 8 + tig * 2;
            if (r0 < M) *(float2*)(C + (size_t)r0 * H + c) = make_float2(acc[mt][nj][0], acc[mt][nj][1]);
            if (r1 < M) *(float2*)(C + (size_t)r1 * H + c) = make_float2(acc[mt][nj][2], acc[mt][nj][3]);
        }
    }
}

// ---------------- fused CSR build (all 4 layers) ----------------
__global__ void init_deg_kernel() {
    int i = blockIdx.x * blockDim.x + threadIdx.x;
    if (i < 4 * N_NODES) g_deg[i] = 1;  // self loop
}

__global__ void hist_all_kernel(const int* __restrict__ e0, const int* __restrict__ e1,
                                const int* __restrict__ e2, const int* __restrict__ e3,
                                int E0, int E1, int E2, int E3) {
    int i = blockIdx.x * blockDim.x + threadIdx.x;
    const int* e; int E; int base;
    if (i < E0) { e = e0; E = E0; base = 0; }
    else { i -= E0;
        if (i < E1) { e = e1; E = E1; base = N_NODES; }
        else { i -= E1;
            if (i < E2) { e = e2; E = E2; base = 2 * N_NODES; }
            else { i -= E2; if (i >= E3) return; e = e3; E = E3; base = 3 * N_NODES; } } }
    atomicAdd(&g_deg[base + e[E + i]], 1);
}

__global__ void scan1_kernel() {
    __shared__ int shm[1024];
    int tid = threadIdx.x;
    int i = blockIdx.x * 1024 + tid;
    int v = (i < 4 * N_NODES) ? g_deg[i] : 0;
    shm[tid] = v;
    __syncthreads();
    for (int off = 1; off < 1024; off <<= 1) {
        int t = (tid >= off) ? shm[tid - off] : 0;
        __syncthreads();
        shm[tid] += t;
        __syncthreads();
    }
    if (i < 4 * N_NODES) g_rowptr[i] = shm[tid] - v;
    if (tid == 1023) g_bsum[blockIdx.x] = shm[1023];
}

__global__ void scan2_kernel(int nb) {
    __shared__ int shm[512];
    int tid = threadIdx.x;
    int v = (tid < nb) ? g_bsum[tid] : 0;
    shm[tid] = v;
    __syncthreads();
    for (int off = 1; off < 512; off <<= 1) {
        int t = (tid >= off) ? shm[tid - off] : 0;
        __syncthreads();
        shm[tid] += t;
        __syncthreads();
    }
    if (tid < nb) g_bsum[tid] = shm[tid] - v;
}

__global__ void scan3_kernel() {
    int i = blockIdx.x * blockDim.x + threadIdx.x;
    if (i >= 4 * N_NODES) return;
    int r = g_rowptr[i] + g_bsum[i >> 10];
    g_rowptr[i] = r;
    int layer = i / N_NODES;
    g_srcs[r] = i - layer * N_NODES;  // self loop first
    g_cursor[i] = r + 1;
}

__global__ void scatter_all_kernel(const int* __restrict__ e0, const int* __restrict__ e1,
                                   const int* __restrict__ e2, const int* __restrict__ e3,
                                   int E0, int E1, int E2, int E3) {
    int i = blockIdx.x * blockDim.x + threadIdx.x;
    const int* e; int E; int base;
    if (i < E0) { e = e0; E = E0; base = 0; }
    else { i -= E0;
        if (i < E1) { e = e1; E = E1; base = N_NODES; }
        else { i -= E1;
            if (i < E2) { e = e2; E = E2; base = 2 * N_NODES; }
            else { i -= E2; if (i >= E3) return; e = e3; E = E3; base = 3 * N_NODES; } } }
    int src = e[i];
    int dst = e[E + i];
    int pos = atomicAdd(&g_cursor[base + dst], 1);
    g_srcs[pos] = src;
}

// -- fused GATv2 softmax-aggregate: warp/dst, dual-stream, depth-1 prefetch,
//    parity-packed 6-shfl dual reduction; [nodeBase, nodeEnd) range --
__global__ void gat_agg_kernel(const float* __restrict__ xl, const float* __restrict__ xr,
                               const float* __restrict__ att, const float* __restrict__ bias,
                               float* __restrict__ hout, int layerBase,
                               int nodeBase, int nodeEnd) {
    int warp = (blockIdx.x * blockDim.x + threadIdx.x) >> 5;
    int lane = threadIdx.x & 31;
    int v = nodeBase + warp;
    if (v >= nodeEnd) return;
    bool odd = lane & 1;

    float4 xrv = __ldcs(((const float4*)(xr + (size_t)v * H)) + lane);
    float4 at = ((const float4*)att)[lane];
    float4 bv = ((const float4*)bias)[lane];

    int beg = g_rowptr[layerBase + v];
    int cnt = g_deg[layerBase + v];

    float m0 = -1e30f, s0 = 0.f, a0x = 0.f, a0y = 0.f, a0z = 0.f, a0w = 0.f;
    float m1 = -1e30f, s1 = 0.f, a1x = 0.f, a1y = 0.f, a1z = 0.f, a1w = 0.f;

    int c0 = __ldg(&g_srcs[beg]);
    int c1 = (cnt > 1) ? __ldg(&g_srcs[beg + 1]) : c0;
    float4 a = __ldg((const float4*)(xl + (size_t)c0 * H) + lane);
    float4 b = __ldg((const float4*)(xl + (size_t)c1 * H) + lane);

    for (int j = 0; j < cnt; j += 2) {
        int n0 = (j + 2 < cnt) ? __ldg(&g_srcs[beg + j + 2]) : c0;
        int n1 = (j + 3 < cnt) ? __ldg(&g_srcs[beg + j + 3]) : n0;
        float4 na = __ldg((const float4*)(xl + (size_t)n0 * H) + lane);
        float4 nb = __ldg((const float4*)(xl + (size_t)n1 * H) + lane);

        bool has1 = (j + 1) < cnt;
        float tx0 = a.x + xrv.x, ty0 = a.y + xrv.y, tz0 = a.z + xrv.z, tw0 = a.w + xrv.w;
        float tx1 = b.x + xrv.x, ty1 = b.y + xrv.y, tz1 = b.z + xrv.z, tw1 = b.w + xrv.w;
        tx0 = fmaxf(tx0, 0.f) + NEG_SLOPE * fminf(tx0, 0.f);
        ty0 = fmaxf(ty0, 0.f) + NEG_SLOPE * fminf(ty0, 0.f);
        tz0 = fmaxf(tz0, 0.f) + NEG_SLOPE * fminf(tz0, 0.f);
        tw0 = fmaxf(tw0, 0.f) + NEG_SLOPE * fminf(tw0, 0.f);
        tx1 = fmaxf(tx1, 0.f) + NEG_SLOPE * fminf(tx1, 0.f);
        ty1 = fmaxf(ty1, 0.f) + NEG_SLOPE * fminf(ty1, 0.f);
        tz1 = fmaxf(tz1, 0.f) + NEG_SLOPE * fminf(tz1, 0.f);
        tw1 = fmaxf(tw1, 0.f) + NEG_SLOPE * fminf(tw1, 0.f);
        float d0 = tx0 * at.x + ty0 * at.y + tz0 * at.z + tw0 * at.w;
        float d1 = tx1 * at.x + ty1 * at.y + tz1 * at.z + tw1 * at.w;

        float send = odd ? d0 : d1;
        float recv = __shfl_xor_sync(0xffffffffu, send, 1);
        float s = odd ? (d1 + recv) : (d0 + recv);
#pragma unroll
        for (int off = 2; off < 32; off <<= 1)
            s += __shfl_xor_sync(0xffffffffu, s, off);
        float t = __shfl_xor_sync(0xffffffffu, s, 1);
        d0 = odd ? t : s;
        d1 = odd ? s : t;

        {
            float nm = fmaxf(m0, d0);
            float sc = __expf(m0 - nm);
            float ex = __expf(d0 - nm);
            s0 = s0 * sc + ex;
            a0x = a0x * sc + ex * a.x;
            a0y = a0y * sc + ex * a.y;
            a0z = a0z * sc + ex * a.z;
            a0w = a0w * sc + ex * a.w;
            m0 = nm;
        }
        if (has1) {
            float nm = fmaxf(m1, d1);
            float sc = __expf(m1 - nm);
            float ex = __expf(d1 - nm);
            s1 = s1 * sc + ex;
            a1x = a1x * sc + ex * b.x;
            a1y = a1y * sc + ex * b.y;
            a1z = a1z * sc + ex * b.z;
            a1w = a1w * sc + ex * b.w;
            m1 = nm;
        }
        a = na; b = nb;
    }

    float nm = fmaxf(m0, m1);
    float sc0 = __expf(m0 - nm);
    float sc1 = __expf(m1 - nm);
    float s = s0 * sc0 + s1 * sc1;
    float inv = 1.f / s;
    float4 o;
    o.x = (a0x * sc0 + a1x * sc1) * inv + bv.x;
    o.y = (a0y * sc0 + a1y * sc1) * inv + bv.y;
    o.z = (a0z * sc0 + a1z * sc1) * inv + bv.z;
    o.w = (a0w * sc0 + a1w * sc1) * inv + bv.w;
    __stcs(((float4*)(hout + (size_t)v * H)) + lane, o);
}

// ---------------- pooling + output head ----------------
__global__ void zero_pooled_kernel() {
    int i = blockIdx.x * blockDim.x + threadIdx.x;
    if (i < NG * H) g_pooled[i] = 0.f;
}

__global__ void pool_kernel(const float* __restrict__ h, const int* __restrict__ ground,
                            const int* __restrict__ batch, int ng) {
    __shared__ float acc[NG * H];
    int tid = threadIdx.x;
    for (int i = tid; i < NG * H; i += 128) acc[i] = 0.f;
    __syncthreads();
    for (int g = blockIdx.x; g < ng; g += gridDim.x) {
        int v = ground[g];
        int b = batch[g];
        acc[b * H + tid] += h[(size_t)v * H + tid];
    }
    __syncthreads();
    for (int i = tid; i < NG * H; i += 128) {
        float x = acc[i];
        if (x != 0.f) atomicAdd(&g_pooled[i], x);
    }
}

__global__ void final_kernel(const float* __restrict__ W, const float* __restrict__ b,
                             float* __restrict__ out) {
    int g = blockIdx.x;
    int o = threadIdx.x;
    float acc = b[o];
#pragma unroll
    for (int k = 0; k < H; k++) acc += g_pooled[g * H + k] * W[k * F_OUT + o];
    out[g * F_OUT + o] = acc;
}

// ---------------- launch ----------------
extern "C" void kernel_launch(void* const* d_in, const int* in_sizes, int n_in,
                              void* d_out, int out_size) {
    const float* x      = (const float*)d_in[0];
    const int*   e0     = (const int*)d_in[1];   // edge_index        (layer 0)
    const int*   e2     = (const int*)d_in[2];   // subgraph_edge     (layer 2)
    const int*   e1     = (const int*)d_in[3];   // node_subnode      (layer 1)
    const int*   e3     = (const int*)d_in[4];   // subnode_node      (layer 3)
    const int*   ground = (const int*)d_in[5];
    const int*   batch  = (const int*)d_in[7];
    const float* embW   = (const float*)d_in[8];
    const float* embb   = (const float*)d_in[9];
    const float* Wl     = (const float*)d_in[10];
    const float* Wr     = (const float*)d_in[11];
    const float* att    = (const float*)d_in[12];
    const float* bias   = (const float*)d_in[13];
    const float* outW   = (const float*)d_in[14];
    const float* outb   = (const float*)d_in[15];
    int ng = in_sizes[5];

    int E0 = in_sizes[1] / 2, E1 = in_sizes[3] / 2, E2 = in_sizes[2] / 2, E3 = in_sizes[4] / 2;
    int Etot = E0 + E1 + E2 + E3;

    float *hA, *hB, *xlA, *xrA, *xlB, *xrB;
    __nv_bfloat16 *wh, *wl;
    cudaGetSymbolAddress((void**)&hA, g_hA);
    cudaGetSymbolAddress((void**)&hB, g_hB);
    cudaGetSymbolAddress((void**)&xlA, g_xlA);
    cudaGetSymbolAddress((void**)&xrA, g_xrA);
    cudaGetSymbolAddress((void**)&xlB, g_xlB);
    cudaGetSymbolAddress((void**)&xrB, g_xrB);
    cudaGetSymbolAddress((void**)&wh, g_wh);
    cudaGetSymbolAddress((void**)&wl, g_wl);

    cudaFuncSetAttribute(mma_gemm, cudaFuncAttributeMaxDynamicSharedMemorySize, SM_TOTAL);

    static cudaStream_t s2 = nullptr;
    static cudaEvent_t evFork = nullptr, evJoin = nullptr;
    static cudaEvent_t evA[3] = {}, evG[3] = {};
    if (!s2) {
        cudaStreamCreateWithFlags(&s2, cudaStreamNonBlocking);
        cudaEventCreateWithFlags(&evFork, cudaEventDisableTiming);
        cudaEventCreateWithFlags(&evJoin, cudaEventDisableTiming);
        for (int i = 0; i < 3; i++) {
            cudaEventCreateWithFlags(&evA[i], cudaEventDisableTiming);
            cudaEventCreateWithFlags(&evG[i], cudaEventDisableTiming);
        }
    }

    // ---- fork: CSR build chain on side stream ----
    cudaEventRecord(evFork, 0);
    cudaStreamWaitEvent(s2, evFork, 0);

    int scanBlocks = (4 * N_NODES + 1023) / 1024;
    init_deg_kernel<<<(4 * N_NODES + 255) / 256, 256, 0, s2>>>();
    hist_all_kernel<<<(Etot + 255) / 256, 256, 0, s2>>>(e0, e1, e2, e3, E0, E1, E2, E3);
    scan1_kernel<<<scanBlocks, 1024, 0, s2>>>();
    scan2_kernel<<<1, 512, 0, s2>>>(scanBlocks);
    scan3_kernel<<<(4 * N_NODES + 255) / 256, 256, 0, s2>>>();
    scatter_all_kernel<<<(Etot + 255) / 256, 256, 0, s2>>>(e0, e1, e2, e3, E0, E1, E2, E3);
    zero_pooled_kernel<<<(NG * H + 255) / 256, 256, 0, s2>>>();
    cudaEventRecord(evJoin, s2);

    // ---- main stream: emb -> wprep -> gemm0 (full) ----
    emb_kernel<<<(N_NODES + 15) / 16, 128>>>(x, embW, embb, hA);
    wprep_kernel<<<(8 * H * H + 255) / 256, 256>>>(Wl, Wr);

    const int ROWS2 = N_NODES - CHUNK;                 // 49952
    const int GB1 = CHUNK / 64;                        // 782
    const int GB2 = (ROWS2 + 63) / 64;                 // 781
    dim3 gfull((N_NODES + 63) / 64, 2);
    dim3 gc1(GB1, 2), gc2(GB2, 2);
    const int AB1 = (CHUNK * 32 + 255) / 256;          // agg chunk A blocks
    const int AB2 = (ROWS2 * 32 + 255) / 256;

    float* hin = hA;
    float* hout = hB;
    float *xl = xlA, *xr = xrA, *xln = xlB, *xrn = xrB;

    mma_gemm<<<gfull, 256, SM_TOTAL>>>(hin, wh, wl, wh + H * H, wl + H * H, xl, xr, N_NODES, 0);

    cudaStreamWaitEvent(0, evJoin, 0);

    for (int l = 0; l < 4; l++) {
        const float* at = att + l * H;
        const float* bs = bias + l * H;
        int lb = l * N_NODES;
        if (l < 3) {
            const __nv_bfloat16* nwlh = wh + (2 * (l + 1)) * H * H;
            const __nv_bfloat16* nwll = wl + (2 * (l + 1)) * H * H;
            const __nv_bfloat16* nwrh = wh + (2 * (l + 1) + 1) * H * H;
            const __nv_bfloat16* nwrl = wl + (2 * (l + 1) + 1) * H * H;

            // agg chunk A -> event -> gemm chunk1 on s2 (overlaps agg chunk B)
            gat_agg_kernel<<<AB1, 256>>>(xl, xr, at, bs, hout, lb, 0, CHUNK);
            cudaEventRecord(evA[l], 0);
            gat_agg_kernel<<<AB2, 256>>>(xl, xr, at, bs, hout, lb, CHUNK, N_NODES);

            cudaStreamWaitEvent(s2, evA[l], 0);
            mma_gemm<<<gc1, 256, SM_TOTAL, s2>>>(hout, nwlh, nwll, nwrh, nwrl,
                                                 xln, xrn, CHUNK, 0);
            cudaEventRecord(evG[l], s2);

            // gemm chunk2 on main (after agg chunk B in program order)
            mma_gemm<<<gc2, 256, SM_TOTAL>>>(hout, nwlh, nwll, nwrh, nwrl,
                                             xln, xrn, N_NODES, CHUNK);
            cudaStreamWaitEvent(0, evG[l], 0);

            float* t = hin; hin = hout; hout = t;
            float* u;
            u = xl; xl = xln; xln = u;
            u = xr; xr = xrn; xrn = u;
        } else {
            gat_agg_kernel<<<(N_NODES * 32 + 255) / 256, 256>>>(xl, xr, at, bs, hout, lb, 0, N_NODES);
            float* t = hin; hin = hout; hout = t;
        }
    }

    pool_kernel<<<640, 128>>>(hin, ground, batch, ng);
    final_kernel<<<NG, F_OUT>>>(outW, outb, (float*)d_out);
}

// round 13
// speedup vs baseline: 1.2321x; 1.0295x over previous
#include <cuda_runtime.h>
#include <cuda_bf16.h>
#include <cstdint>

#define N_NODES 100000
#define H 128
#define F_IN 32
#define F_OUT 16
#define NG 64
#define NEG_SLOPE 0.2f
#define SRC_MAX 2800000   // sum(E) + 4*N self loops

// ---------------- device scratch ----------------
__device__ float g_hA[N_NODES * H];
__device__ float g_hB[N_NODES * H];
__device__ __nv_bfloat16 g_xl[N_NODES * H];   // bf16: halves agg gather traffic
__device__ float g_xr[N_NODES * H];
__device__ int   g_deg[4 * N_NODES];
__device__ int   g_rowptr[4 * N_NODES];
__device__ int   g_cursor[4 * N_NODES];
__device__ int   g_srcs[SRC_MAX];
__device__ int   g_bsum[512];
__device__ float g_pooled[NG * H];
// prepared weights: [4 layers][Wl,Wr] transposed to [n][k] row-major, bf16 hi/lo
__device__ __nv_bfloat16 g_wh[8 * H * H];
__device__ __nv_bfloat16 g_wl[8 * H * H];

// ---------------- mma.sync helpers (sm_80 path, valid on compute_103) ------
__device__ __forceinline__ uint32_t smem_to_u32(const void* p) {
    uint32_t a;
    asm("{ .reg .u64 t; cvta.to.shared.u64 t, %1; cvt.u32.u64 %0, t; }" : "=r"(a) : "l"(p));
    return a;
}
__device__ __forceinline__ void ldsm_x4(uint32_t r[4], uint32_t addr) {
    asm volatile("ldmatrix.sync.aligned.m8n8.x4.shared.b16 {%0,%1,%2,%3}, [%4];"
                 : "=r"(r[0]), "=r"(r[1]), "=r"(r[2]), "=r"(r[3]) : "r"(addr));
}
__device__ __forceinline__ void mma_bf16(float c[4], const uint32_t a[4],
                                         uint32_t b0, uint32_t b1) {
    asm volatile(
        "mma.sync.aligned.m16n8k16.row.col.f32.bf16.bf16.f32 "
        "{%0,%1,%2,%3}, {%4,%5,%6,%7}, {%8,%9}, {%0,%1,%2,%3};"
        : "+f"(c[0]), "+f"(c[1]), "+f"(c[2]), "+f"(c[3])
        : "r"(a[0]), "r"(a[1]), "r"(a[2]), "r"(a[3]), "r"(b0), "r"(b1));
}

// tile row: 256 bytes (128 bf16), XOR-swizzled 16B chunks
__device__ __forceinline__ uint32_t tile_off(int row, int kb) {
    return (uint32_t)(row * 256) + (uint32_t)(kb ^ ((row & 7) << 4));
}

// ---------------- embedding ----------------
__global__ void emb_kernel(const float* __restrict__ x, const float* __restrict__ W,
                           const float* __restrict__ b, float* __restrict__ h) {
    __shared__ float sW[F_IN * H];
    __shared__ float sx[16 * F_IN];
    int tid = threadIdx.x;
    for (int i = tid; i < F_IN * H; i += 128) sW[i] = W[i];
    int n0 = blockIdx.x * 16;
    for (int i = tid; i < 16 * F_IN; i += 128) {
        int r = i >> 5;
        int node = n0 + r;
        sx[i] = (node < N_NODES) ? x[node * F_IN + (i & 31)] : 0.f;
    }
    __syncthreads();
    float bb = b[tid];
    for (int r = 0; r < 16; r++) {
        int node = n0 + r;
        if (node >= N_NODES) break;
        float acc = bb;
#pragma unroll
        for (int k = 0; k < F_IN; k++) acc += sx[r * F_IN + k] * sW[k * H + tid];
        h[node * H + tid] = acc;
    }
}

// ---------------- weight prep: transpose + bf16 hi/lo split ----------------
__global__ void wprep_kernel(const float* __restrict__ Wl, const float* __restrict__ Wr) {
    int idx = blockIdx.x * 256 + threadIdx.x;
    if (idx >= 8 * H * H) return;
    int mat = idx >> 14;            // 0..7 = layer*2 + (0=Wl,1=Wr)
    int e = idx & 16383;
    int n = e >> 7, k = e & 127;
    int layer = mat >> 1;
    const float* W = ((mat & 1) ? Wr : Wl) + layer * H * H;
    float v = W[k * H + n];         // transpose: [n][k] = W[k][n]
    __nv_bfloat16 hi = __float2bfloat16(v);
    float lo = v - __bfloat162float(hi);
    g_wh[idx] = hi;
    g_wl[idx] = __float2bfloat16(lo);
}

// ------- HMMA split-bf16 GEMM: 64-row tile, 8 warps of 32x32, 2 blk/SM -----
// blockIdx.y == 0 -> Wl path, output bf16 to Cl16 (agg-only consumer)
// blockIdx.y == 1 -> Wr path, output fp32 to Cr
#define SMA_HI 0
#define SMA_LO 16384
#define SMW_HI 32768
#define SMW_LO 65536
#define SM_TOTAL 98304

__global__ void __launch_bounds__(256, 2) mma_gemm(
    const float* __restrict__ A,
    const __nv_bfloat16* __restrict__ wlh, const __nv_bfloat16* __restrict__ wll,
    const __nv_bfloat16* __restrict__ wrh, const __nv_bfloat16* __restrict__ wrl,
    __nv_bfloat16* __restrict__ Cl16, float* __restrict__ Cr, int M) {
    extern __shared__ char smem[];
    uint32_t sb = smem_to_u32(smem);
    int tid = threadIdx.x;
    int wid = tid >> 5, lane = tid & 31;
    int row0 = blockIdx.x * 64;

    const __nv_bfloat16* whi = (blockIdx.y == 0) ? wlh : wrh;
    const __nv_bfloat16* wlo = (blockIdx.y == 0) ? wll : wrl;

    const float4* A4 = (const float4*)(A + (size_t)row0 * H);
#pragma unroll
    for (int it = 0; it < 8; it++) {
        int g = tid + it * 256;
        int row = g >> 5;
        int k4 = g & 31;
        float4 v = make_float4(0.f, 0.f, 0.f, 0.f);
        if (row0 + row < M) v = A4[g];
        __nv_bfloat16 h0 = __float2bfloat16(v.x);
        __nv_bfloat16 h1 = __float2bfloat16(v.y);
        __nv_bfloat16 h2 = __float2bfloat16(v.z);
        __nv_bfloat16 h3 = __float2bfloat16(v.w);
        __nv_bfloat16 l0 = __float2bfloat16(v.x - __bfloat162float(h0));
        __nv_bfloat16 l1 = __float2bfloat16(v.y - __bfloat162float(h1));
        __nv_bfloat16 l2 = __float2bfloat16(v.z - __bfloat162float(h2));
        __nv_bfloat16 l3 = __float2bfloat16(v.w - __bfloat162float(h3));
        uint2 ph, pl;
        ph.x = (uint32_t)__bfloat16_as_ushort(h0) | ((uint32_t)__bfloat16_as_ushort(h1) << 16);
        ph.y = (uint32_t)__bfloat16_as_ushort(h2) | ((uint32_t)__bfloat16_as_ushort(h3) << 16);
        pl.x = (uint32_t)__bfloat16_as_ushort(l0) | ((uint32_t)__bfloat16_as_ushort(l1) << 16);
        pl.y = (uint32_t)__bfloat16_as_ushort(l2) | ((uint32_t)__bfloat16_as_ushort(l3) << 16);
        uint32_t off = tile_off(row, k4 * 8);
        *(uint2*)(smem + SMA_HI + off) = ph;
        *(uint2*)(smem + SMA_LO + off) = pl;
    }
    const uint2* WH = (const uint2*)whi;
    const uint2* WL = (const uint2*)wlo;
#pragma unroll
    for (int it = 0; it < 16; it++) {
        int g = tid + it * 256;
        int row = g >> 5;
        uint32_t off = tile_off(row, (g & 31) * 8);
        *(uint2*)(smem + SMW_HI + off) = WH[g];
        *(uint2*)(smem + SMW_LO + off) = WL[g];
    }
    __syncthreads();

    int wm = (wid & 1) * 32;
    int wn = (wid >> 1) * 32;

    float acc[2][4][4];
#pragma unroll
    for (int mt = 0; mt < 2; mt++)
#pragma unroll
        for (int nj = 0; nj < 4; nj++)
#pragma unroll
            for (int i = 0; i < 4; i++) acc[mt][nj][i] = 0.f;

    int a_row_off = lane & 15;
    int a_kb_off = (lane >> 4) << 4;
    int b_row_off = (lane & 7) + ((lane >> 4) << 3);
    int b_kb_off = ((lane >> 3) & 1) << 4;

#pragma unroll
    for (int ks = 0; ks < 8; ks++) {
        int kb = ks * 32;
        uint32_t ah[2][4], al[2][4];
#pragma unroll
        for (int mt = 0; mt < 2; mt++) {
            int row = wm + mt * 16 + a_row_off;
            uint32_t off = tile_off(row, kb + a_kb_off);
            ldsm_x4(ah[mt], sb + SMA_HI + off);
            ldsm_x4(al[mt], sb + SMA_LO + off);
        }
        uint32_t bh[2][4], bl[2][4];
#pragma unroll
        for (int ng = 0; ng < 2; ng++) {
            int nrow = wn + ng * 16 + b_row_off;
            uint32_t off = tile_off(nrow, kb + b_kb_off);
            ldsm_x4(bh[ng], sb + SMW_HI + off);
            ldsm_x4(bl[ng], sb + SMW_LO + off);
        }
#pragma unroll
        for (int mt = 0; mt < 2; mt++) {
#pragma unroll
            for (int nj = 0; nj < 4; nj++) {
                int ng = nj >> 1, half = (nj & 1) * 2;
                mma_bf16(acc[mt][nj], ah[mt], bh[ng][half], bh[ng][half + 1]);
                mma_bf16(acc[mt][nj], ah[mt], bl[ng][half], bl[ng][half + 1]);
                mma_bf16(acc[mt][nj], al[mt], bh[ng][half], bh[ng][half + 1]);
            }
        }
    }

    int gid = lane >> 2, tig = lane & 3;
    if (blockIdx.y == 0) {
        // bf16 output (consumed only by gather in agg)
#pragma unroll
        for (int mt = 0; mt < 2; mt++) {
            int r0 = row0 + wm + mt * 16 + gid;
            int r1 = r0 + 8;
#pragma unroll
            for (int nj = 0; nj < 4; nj++) {
                int c = wn + nj * 8 + tig * 2;
                if (r0 < M) {
                    __nv_bfloat162 p = __float22bfloat162_rn(make_float2(acc[mt][nj][0], acc[mt][nj][1]));
                    *(__nv_bfloat162*)(Cl16 + (size_t)r0 * H + c) = p;
                }
                if (r1 < M) {
                    __nv_bfloat162 p = __float22bfloat162_rn(make_float2(acc[mt][nj][2], acc[mt][nj][3]));
                    *(__nv_bfloat162*)(Cl16 + (size_t)r1 * H + c) = p;
                }
            }
        }
    } else {
#pragma unroll
        for (int mt = 0; mt < 2; mt++) {
            int r0 = row0 + wm + mt * 16 + gid;
            int r1 = r0 + 8;
#pragma unroll
            for (int nj = 0; nj < 4; nj++) {
                int c = wn + nj * 8 + tig * 2;
                if (r0 < M) *(float2*)(Cr + (size_t)r0 * H + c) = make_float2(acc[mt][nj][0], acc[mt][nj][1]);
                if (r1 < M) *(float2*)(Cr + (size_t)r1 * H + c) = make_float2(acc[mt][nj][2], acc[mt][nj][3]);
            }
        }
    }
}

// ---------------- fused CSR build (all 4 layers) ----------------
__global__ void init_deg_kernel() {
    int i = blockIdx.x * blockDim.x + threadIdx.x;
    if (i < 4 * N_NODES) g_deg[i] = 1;  // self loop
}

__global__ void hist_all_kernel(const int* __restrict__ e0, const int* __restrict__ e1,
                                const int* __restrict__ e2, const int* __restrict__ e3,
                                int E0, int E1, int E2, int E3) {
    int i = blockIdx.x * blockDim.x + threadIdx.x;
    const int* e; int E; int base;
    if (i < E0) { e = e0; E = E0; base = 0; }
    else { i -= E0;
        if (i < E1) { e = e1; E = E1; base = N_NODES; }
        else { i -= E1;
            if (i < E2) { e = e2; E = E2; base = 2 * N_NODES; }
            else { i -= E2; if (i >= E3) return; e = e3; E = E3; base = 3 * N_NODES; } } }
    atomicAdd(&g_deg[base + e[E + i]], 1);
}

__global__ void scan1_kernel() {
    __shared__ int shm[1024];
    int tid = threadIdx.x;
    int i = blockIdx.x * 1024 + tid;
    int v = (i < 4 * N_NODES) ? g_deg[i] : 0;
    shm[tid] = v;
    __syncthreads();
    for (int off = 1; off < 1024; off <<= 1) {
        int t = (tid >= off) ? shm[tid - off] : 0;
        __syncthreads();
        shm[tid] += t;
        __syncthreads();
    }
    if (i < 4 * N_NODES) g_rowptr[i] = shm[tid] - v;
    if (tid == 1023) g_bsum[blockIdx.x] = shm[1023];
}

__global__ void scan2_kernel(int nb) {
    __shared__ int shm[512];
    int tid = threadIdx.x;
    int v = (tid < nb) ? g_bsum[tid] : 0;
    shm[tid] = v;
    __syncthreads();
    for (int off = 1; off < 512; off <<= 1) {
        int t = (tid >= off) ? shm[tid - off] : 0;
        __syncthreads();
        shm[tid] += t;
        __syncthreads();
    }
    if (tid < nb) g_bsum[tid] = shm[tid] - v;
}

__global__ void scan3_kernel() {
    int i = blockIdx.x * blockDim.x + threadIdx.x;
    if (i >= 4 * N_NODES) return;
    int r = g_rowptr[i] + g_bsum[i >> 10];
    g_rowptr[i] = r;
    int layer = i / N_NODES;
    g_srcs[r] = i - layer * N_NODES;  // self loop first
    g_cursor[i] = r + 1;
}

__global__ void scatter_all_kernel(const int* __restrict__ e0, const int* __restrict__ e1,
                                   const int* __restrict__ e2, const int* __restrict__ e3,
                                   int E0, int E1, int E2, int E3) {
    int i = blockIdx.x * blockDim.x + threadIdx.x;
    const int* e; int E; int base;
    if (i < E0) { e = e0; E = E0; base = 0; }
    else { i -= E0;
        if (i < E1) { e = e1; E = E1; base = N_NODES; }
        else { i -= E1;
            if (i < E2) { e = e2; E = E2; base = 2 * N_NODES; }
            else { i -= E2; if (i >= E3) return; e = e3; E = E3; base = 3 * N_NODES; } } }
    int src = e[i];
    int dst = e[E + i];
    int pos = atomicAdd(&g_cursor[base + dst], 1);
    g_srcs[pos] = src;
}

// -- fused GATv2 softmax-aggregate: warp/dst, dual-stream, depth-1 prefetch,
//    parity-packed 6-shfl dual reduction; xl gathered as bf16 (uint2/lane) --
__device__ __forceinline__ float4 unpack_bf4(uint2 p) {
    float2 lo = __bfloat1622float2(*(__nv_bfloat162*)&p.x);
    float2 hi = __bfloat1622float2(*(__nv_bfloat162*)&p.y);
    return make_float4(lo.x, lo.y, hi.x, hi.y);
}

__global__ void gat_agg_kernel(const __nv_bfloat16* __restrict__ xl,
                               const float* __restrict__ xr,
                               const float* __restrict__ att, const float* __restrict__ bias,
                               float* __restrict__ hout, int layerBase) {
    int warp = (blockIdx.x * blockDim.x + threadIdx.x) >> 5;
    int lane = threadIdx.x & 31;
    if (warp >= N_NODES) return;
    int v = warp;
    bool odd = lane & 1;

    float4 xrv = __ldcs(((const float4*)(xr + (size_t)v * H)) + lane);
    float4 at = ((const float4*)att)[lane];
    float4 bv = ((const float4*)bias)[lane];

    int beg = g_rowptr[layerBase + v];
    int cnt = g_deg[layerBase + v];

    float m0 = -1e30f, s0 = 0.f, a0x = 0.f, a0y = 0.f, a0z = 0.f, a0w = 0.f;
    float m1 = -1e30f, s1 = 0.f, a1x = 0.f, a1y = 0.f, a1z = 0.f, a1w = 0.f;

    int c0 = __ldg(&g_srcs[beg]);
    int c1 = (cnt > 1) ? __ldg(&g_srcs[beg + 1]) : c0;
    uint2 pa = __ldg((const uint2*)(xl + (size_t)c0 * H) + lane);
    uint2 pb = __ldg((const uint2*)(xl + (size_t)c1 * H) + lane);

    for (int j = 0; j < cnt; j += 2) {
        int n0 = (j + 2 < cnt) ? __ldg(&g_srcs[beg + j + 2]) : c0;
        int n1 = (j + 3 < cnt) ? __ldg(&g_srcs[beg + j + 3]) : n0;
        uint2 npa = __ldg((const uint2*)(xl + (size_t)n0 * H) + lane);
        uint2 npb = __ldg((const uint2*)(xl + (size_t)n1 * H) + lane);

        float4 a = unpack_bf4(pa);
        float4 b = unpack_bf4(pb);

        bool has1 = (j + 1) < cnt;
        float tx0 = a.x + xrv.x, ty0 = a.y + xrv.y, tz0 = a.z + xrv.z, tw0 = a.w + xrv.w;
        float tx1 = b.x + xrv.x, ty1 = b.y + xrv.y, tz1 = b.z + xrv.z, tw1 = b.w + xrv.w;
        tx0 = fmaxf(tx0, 0.f) + NEG_SLOPE * fminf(tx0, 0.f);
        ty0 = fmaxf(ty0, 0.f) + NEG_SLOPE * fminf(ty0, 0.f);
        tz0 = fmaxf(tz0, 0.f) + NEG_SLOPE * fminf(tz0, 0.f);
        tw0 = fmaxf(tw0, 0.f) + NEG_SLOPE * fminf(tw0, 0.f);
        tx1 = fmaxf(tx1, 0.f) + NEG_SLOPE * fminf(tx1, 0.f);
        ty1 = fmaxf(ty1, 0.f) + NEG_SLOPE * fminf(ty1, 0.f);
        tz1 = fmaxf(tz1, 0.f) + NEG_SLOPE * fminf(tz1, 0.f);
        tw1 = fmaxf(tw1, 0.f) + NEG_SLOPE * fminf(tw1, 0.f);
        float d0 = tx0 * at.x + ty0 * at.y + tz0 * at.z + tw0 * at.w;
        float d1 = tx1 * at.x + ty1 * at.y + tz1 * at.z + tw1 * at.w;

        float send = odd ? d0 : d1;
        float recv = __shfl_xor_sync(0xffffffffu, send, 1);
        float s = odd ? (d1 + recv) : (d0 + recv);
#pragma unroll
        for (int off = 2; off < 32; off <<= 1)
            s += __shfl_xor_sync(0xffffffffu, s, off);
        float t = __shfl_xor_sync(0xffffffffu, s, 1);
        d0 = odd ? t : s;
        d1 = odd ? s : t;

        {
            float nm = fmaxf(m0, d0);
            float sc = __expf(m0 - nm);
            float ex = __expf(d0 - nm);
            s0 = s0 * sc + ex;
            a0x = a0x * sc + ex * a.x;
            a0y = a0y * sc + ex * a.y;
            a0z = a0z * sc + ex * a.z;
            a0w = a0w * sc + ex * a.w;
            m0 = nm;
        }
        if (has1) {
            float nm = fmaxf(m1, d1);
            float sc = __expf(m1 - nm);
            float ex = __expf(d1 - nm);
            s1 = s1 * sc + ex;
            a1x = a1x * sc + ex * b.x;
            a1y = a1y * sc + ex * b.y;
            a1z = a1z * sc + ex * b.z;
            a1w = a1w * sc + ex * b.w;
            m1 = nm;
        }
        pa = npa; pb = npb;
    }

    float nm = fmaxf(m0, m1);
    float sc0 = __expf(m0 - nm);
    float sc1 = __expf(m1 - nm);
    float s = s0 * sc0 + s1 * sc1;
    float inv = 1.f / s;
    float4 o;
    o.x = (a0x * sc0 + a1x * sc1) * inv + bv.x;
    o.y = (a0y * sc0 + a1y * sc1) * inv + bv.y;
    o.z = (a0z * sc0 + a1z * sc1) * inv + bv.z;
    o.w = (a0w * sc0 + a1w * sc1) * inv + bv.w;
    __stcs(((float4*)(hout + (size_t)v * H)) + lane, o);
}

// ---------------- pooling + output head ----------------
__global__ void zero_pooled_kernel() {
    int i = blockIdx.x * blockDim.x + threadIdx.x;
    if (i < NG * H) g_pooled[i] = 0.f;
}

__global__ void pool_kernel(const float* __restrict__ h, const int* __restrict__ ground,
                            const int* __restrict__ batch, int ng) {
    __shared__ float acc[NG * H];
    int tid = threadIdx.x;
    for (int i = tid; i < NG * H; i += 128) acc[i] = 0.f;
    __syncthreads();
    for (int g = blockIdx.x; g < ng; g += gridDim.x) {
        int v = ground[g];
        int b = batch[g];
        acc[b * H + tid] += h[(size_t)v * H + tid];
    }
    __syncthreads();
    for (int i = tid; i < NG * H; i += 128) {
        float x = acc[i];
        if (x != 0.f) atomicAdd(&g_pooled[i], x);
    }
}

__global__ void final_kernel(const float* __restrict__ W, const float* __restrict__ b,
                             float* __restrict__ out) {
    int g = blockIdx.x;
    int o = threadIdx.x;
    float acc = b[o];
#pragma unroll
    for (int k = 0; k < H; k++) acc += g_pooled[g * H + k] * W[k * F_OUT + o];
    out[g * F_OUT + o] = acc;
}

// ---------------- launch ----------------
extern "C" void kernel_launch(void* const* d_in, const int* in_sizes, int n_in,
                              void* d_out, int out_size) {
    const float* x      = (const float*)d_in[0];
    const int*   e0     = (const int*)d_in[1];   // edge_index        (layer 0)
    const int*   e2     = (const int*)d_in[2];   // subgraph_edge     (layer 2)
    const int*   e1     = (const int*)d_in[3];   // node_subnode      (layer 1)
    const int*   e3     = (const int*)d_in[4];   // subnode_node      (layer 3)
    const int*   ground = (const int*)d_in[5];
    const int*   batch  = (const int*)d_in[7];
    const float* embW   = (const float*)d_in[8];
    const float* embb   = (const float*)d_in[9];
    const float* Wl     = (const float*)d_in[10];
    const float* Wr     = (const float*)d_in[11];
    const float* att    = (const float*)d_in[12];
    const float* bias   = (const float*)d_in[13];
    const float* outW   = (const float*)d_in[14];
    const float* outb   = (const float*)d_in[15];
    int ng = in_sizes[5];

    int E0 = in_sizes[1] / 2, E1 = in_sizes[3] / 2, E2 = in_sizes[2] / 2, E3 = in_sizes[4] / 2;
    int Etot = E0 + E1 + E2 + E3;

    float *hA, *hB, *xrp;
    __nv_bfloat16 *xlp, *wh, *wl;
    cudaGetSymbolAddress((void**)&hA, g_hA);
    cudaGetSymbolAddress((void**)&hB, g_hB);
    cudaGetSymbolAddress((void**)&xlp, g_xl);
    cudaGetSymbolAddress((void**)&xrp, g_xr);
    cudaGetSymbolAddress((void**)&wh, g_wh);
    cudaGetSymbolAddress((void**)&wl, g_wl);

    cudaFuncSetAttribute(mma_gemm, cudaFuncAttributeMaxDynamicSharedMemorySize, SM_TOTAL);

    static cudaStream_t s2 = nullptr;
    static cudaEvent_t evFork = nullptr, evJoin = nullptr;
    if (!s2) {
        cudaStreamCreateWithFlags(&s2, cudaStreamNonBlocking);
        cudaEventCreateWithFlags(&evFork, cudaEventDisableTiming);
        cudaEventCreateWithFlags(&evJoin, cudaEventDisableTiming);
    }

    // ---- fork: CSR build chain on side stream ----
    cudaEventRecord(evFork, 0);
    cudaStreamWaitEvent(s2, evFork, 0);

    int scanBlocks = (4 * N_NODES + 1023) / 1024;
    init_deg_kernel<<<(4 * N_NODES + 255) / 256, 256, 0, s2>>>();
    hist_all_kernel<<<(Etot + 255) / 256, 256, 0, s2>>>(e0, e1, e2, e3, E0, E1, E2, E3);
    scan1_kernel<<<scanBlocks, 1024, 0, s2>>>();
    scan2_kernel<<<1, 512, 0, s2>>>(scanBlocks);
    scan3_kernel<<<(4 * N_NODES + 255) / 256, 256, 0, s2>>>();
    scatter_all_kernel<<<(Etot + 255) / 256, 256, 0, s2>>>(e0, e1, e2, e3, E0, E1, E2, E3);
    zero_pooled_kernel<<<(NG * H + 255) / 256, 256, 0, s2>>>();
    cudaEventRecord(evJoin, s2);

    // ---- main stream: emb -> wprep -> gemm0 ----
    emb_kernel<<<(N_NODES + 15) / 16, 128>>>(x, embW, embb, hA);
    wprep_kernel<<<(8 * H * H + 255) / 256, 256>>>(Wl, Wr);

    dim3 ggrid((N_NODES + 63) / 64, 2);
    float* hin = hA;
    float* hout = hB;

    mma_gemm<<<ggrid, 256, SM_TOTAL>>>(hin, wh, wl, wh + H * H, wl + H * H, xlp, xrp, N_NODES);

    cudaStreamWaitEvent(0, evJoin, 0);

    for (int l = 0; l < 4; l++) {
        if (l > 0) {
            mma_gemm<<<ggrid, 256, SM_TOTAL>>>(hin, wh + (2 * l) * H * H, wl + (2 * l) * H * H,
                                               wh + (2 * l + 1) * H * H, wl + (2 * l + 1) * H * H,
                                               xlp, xrp, N_NODES);
        }
        gat_agg_kernel<<<(N_NODES * 32 + 255) / 256, 256>>>(
            xlp, xrp, att + l * H, bias + l * H, hout, l * N_NODES);
        float* t = hin; hin = hout; hout = t;
    }

    pool_kernel<<<640, 128>>>(hin, ground, batch, ng);
    final_kernel<<<NG, F_OUT>>>(outW, outb, (float*)d_out);
}

// round 14
// speedup vs baseline: 1.2493x; 1.0140x over previous
#include <cuda_runtime.h>
#include <cuda_bf16.h>
#include <cstdint>

#define N_NODES 100000
#define H 128
#define F_IN 32
#define F_OUT 16
#define NG 64
#define NEG_SLOPE 0.2f
#define SRC_MAX 2800000   // sum(E) + 4*N self loops
#define POOL_BLKS 128

// ---------------- device scratch ----------------
__device__ float g_hA[N_NODES * H];
__device__ float g_hB[N_NODES * H];
__device__ __nv_bfloat16 g_xl[N_NODES * H];   // bf16: halves agg gather traffic
__device__ float g_xr[N_NODES * H];
__device__ int   g_deg[4 * N_NODES];
__device__ int   g_rowptr[4 * N_NODES];
__device__ int   g_cursor[4 * N_NODES];
__device__ int   g_srcs[SRC_MAX];
__device__ int   g_bsum[512];
__device__ float g_pooled[NG * H];
__device__ float g_part[POOL_BLKS * NG * H];
// prepared weights: [4 layers][Wl,Wr] transposed to [n][k] row-major, bf16 hi/lo
__device__ __nv_bfloat16 g_wh[8 * H * H];
__device__ __nv_bfloat16 g_wl[8 * H * H];
// emb weight transposed [n][k] = [128][32], bf16 hi/lo
__device__ __nv_bfloat16 g_ewh[H * F_IN];
__device__ __nv_bfloat16 g_ewl[H * F_IN];

// ---------------- mma.sync helpers ----------------
__device__ __forceinline__ uint32_t smem_to_u32(const void* p) {
    uint32_t a;
    asm("{ .reg .u64 t; cvta.to.shared.u64 t, %1; cvt.u32.u64 %0, t; }" : "=r"(a) : "l"(p));
    return a;
}
__device__ __forceinline__ void ldsm_x4(uint32_t r[4], uint32_t addr) {
    asm volatile("ldmatrix.sync.aligned.m8n8.x4.shared.b16 {%0,%1,%2,%3}, [%4];"
                 : "=r"(r[0]), "=r"(r[1]), "=r"(r[2]), "=r"(r[3]) : "r"(addr));
}
__device__ __forceinline__ void mma_bf16(float c[4], const uint32_t a[4],
                                         uint32_t b0, uint32_t b1) {
    asm volatile(
        "mma.sync.aligned.m16n8k16.row.col.f32.bf16.bf16.f32 "
        "{%0,%1,%2,%3}, {%4,%5,%6,%7}, {%8,%9}, {%0,%1,%2,%3};"
        : "+f"(c[0]), "+f"(c[1]), "+f"(c[2]), "+f"(c[3])
        : "r"(a[0]), "r"(a[1]), "r"(a[2]), "r"(a[3]), "r"(b0), "r"(b1));
}

// 256B-row tile (main gemm), XOR-swizzled 16B chunks
__device__ __forceinline__ uint32_t tile_off(int row, int kb) {
    return (uint32_t)(row * 256) + (uint32_t)(kb ^ ((row & 7) << 4));
}
// 128B-row tile (emb gemm)
__device__ __forceinline__ uint32_t tile_off128(int row, int kb) {
    return (uint32_t)(row * 128) + (uint32_t)(kb ^ ((row & 7) << 4));
}

__device__ __forceinline__ void split_pack(float4 v, uint2& ph, uint2& pl) {
    __nv_bfloat16 h0 = __float2bfloat16(v.x);
    __nv_bfloat16 h1 = __float2bfloat16(v.y);
    __nv_bfloat16 h2 = __float2bfloat16(v.z);
    __nv_bfloat16 h3 = __float2bfloat16(v.w);
    __nv_bfloat16 l0 = __float2bfloat16(v.x - __bfloat162float(h0));
    __nv_bfloat16 l1 = __float2bfloat16(v.y - __bfloat162float(h1));
    __nv_bfloat16 l2 = __float2bfloat16(v.z - __bfloat162float(h2));
    __nv_bfloat16 l3 = __float2bfloat16(v.w - __bfloat162float(h3));
    ph.x = (uint32_t)__bfloat16_as_ushort(h0) | ((uint32_t)__bfloat16_as_ushort(h1) << 16);
    ph.y = (uint32_t)__bfloat16_as_ushort(h2) | ((uint32_t)__bfloat16_as_ushort(h3) << 16);
    pl.x = (uint32_t)__bfloat16_as_ushort(l0) | ((uint32_t)__bfloat16_as_ushort(l1) << 16);
    pl.y = (uint32_t)__bfloat16_as_ushort(l2) | ((uint32_t)__bfloat16_as_ushort(l3) << 16);
}

// ---------------- weight prep ----------------
__global__ void wprep_kernel(const float* __restrict__ Wl, const float* __restrict__ Wr) {
    int idx = blockIdx.x * 256 + threadIdx.x;
    if (idx >= 8 * H * H) return;
    int mat = idx >> 14;
    int e = idx & 16383;
    int n = e >> 7, k = e & 127;
    int layer = mat >> 1;
    const float* W = ((mat & 1) ? Wr : Wl) + layer * H * H;
    float v = W[k * H + n];
    __nv_bfloat16 hi = __float2bfloat16(v);
    float lo = v - __bfloat162float(hi);
    g_wh[idx] = hi;
    g_wl[idx] = __float2bfloat16(lo);
}

__global__ void wprep_emb_kernel(const float* __restrict__ W /*32x128*/) {
    int idx = blockIdx.x * 256 + threadIdx.x;
    if (idx >= H * F_IN) return;
    int n = idx >> 5, k = idx & 31;
    float v = W[k * H + n];
    __nv_bfloat16 hi = __float2bfloat16(v);
    float lo = v - __bfloat162float(hi);
    g_ewh[idx] = hi;
    g_ewl[idx] = __float2bfloat16(lo);
}

// ---------------- emb via HMMA: h[64-row tile,128] = x @ embW^T(prep) + b ---
// smem: A hi/lo 8KB each, W hi/lo 16KB each = 48KB. 256 thr, 8 warps 32x32.
#define ESA_HI 0
#define ESA_LO 8192
#define ESW_HI 16384
#define ESW_LO 32768
#define ESM_TOTAL 49152

__global__ void __launch_bounds__(256, 2) emb_mma(
    const float* __restrict__ x, const float* __restrict__ eb,
    float* __restrict__ h, int M) {
    extern __shared__ char smem[];
    uint32_t sb = smem_to_u32(smem);
    int tid = threadIdx.x;
    int wid = tid >> 5, lane = tid & 31;
    int row0 = blockIdx.x * 64;

    // A: 64 rows x 32 fp32 -> bf16 hi/lo, 128B swizzled rows
    const float4* X4 = (const float4*)(x + (size_t)row0 * F_IN);
#pragma unroll
    for (int it = 0; it < 2; it++) {
        int g = tid + it * 256;          // 0..511 float4
        int row = g >> 3;
        int k4 = g & 7;
        float4 v = make_float4(0.f, 0.f, 0.f, 0.f);
        if (row0 + row < M) v = X4[g];
        uint2 ph, pl;
        split_pack(v, ph, pl);
        uint32_t off = tile_off128(row, k4 * 8);
        *(uint2*)(smem + ESA_HI + off) = ph;
        *(uint2*)(smem + ESA_LO + off) = pl;
    }
    // W: 128 n-rows x 32 bf16
    const uint2* WH = (const uint2*)g_ewh;
    const uint2* WL = (const uint2*)g_ewl;
#pragma unroll
    for (int it = 0; it < 4; it++) {
        int g = tid + it * 256;          // 0..1023 uint2
        int row = g >> 3;
        uint32_t off = tile_off128(row, (g & 7) * 8);
        *(uint2*)(smem + ESW_HI + off) = WH[g];
        *(uint2*)(smem + ESW_LO + off) = WL[g];
    }
    __syncthreads();

    int wm = (wid & 1) * 32;
    int wn = (wid >> 1) * 32;

    float acc[2][4][4];
#pragma unroll
    for (int mt = 0; mt < 2; mt++)
#pragma unroll
        for (int nj = 0; nj < 4; nj++)
#pragma unroll
            for (int i = 0; i < 4; i++) acc[mt][nj][i] = 0.f;

    int a_row_off = lane & 15;
    int a_kb_off = (lane >> 4) << 4;
    int b_row_off = (lane & 7) + ((lane >> 4) << 3);
    int b_kb_off = ((lane >> 3) & 1) << 4;

#pragma unroll
    for (int ks = 0; ks < 2; ks++) {
        int kb = ks * 32;
        uint32_t ah[2][4], al[2][4];
#pragma unroll
        for (int mt = 0; mt < 2; mt++) {
            int row = wm + mt * 16 + a_row_off;
            uint32_t off = tile_off128(row, kb + a_kb_off);
            ldsm_x4(ah[mt], sb + ESA_HI + off);
            ldsm_x4(al[mt], sb + ESA_LO + off);
        }
        uint32_t bh[2][4], bl[2][4];
#pragma unroll
        for (int ng = 0; ng < 2; ng++) {
            int nrow = wn + ng * 16 + b_row_off;
            uint32_t off = tile_off128(nrow, kb + b_kb_off);
            ldsm_x4(bh[ng], sb + ESW_HI + off);
            ldsm_x4(bl[ng], sb + ESW_LO + off);
        }
#pragma unroll
        for (int mt = 0; mt < 2; mt++) {
#pragma unroll
            for (int nj = 0; nj < 4; nj++) {
                int ng = nj >> 1, half = (nj & 1) * 2;
                mma_bf16(acc[mt][nj], ah[mt], bh[ng][half], bh[ng][half + 1]);
                mma_bf16(acc[mt][nj], ah[mt], bl[ng][half], bl[ng][half + 1]);
                mma_bf16(acc[mt][nj], al[mt], bh[ng][half], bh[ng][half + 1]);
            }
        }
    }

    int gid = lane >> 2, tig = lane & 3;
#pragma unroll
    for (int mt = 0; mt < 2; mt++) {
        int r0 = row0 + wm + mt * 16 + gid;
        int r1 = r0 + 8;
#pragma unroll
        for (int nj = 0; nj < 4; nj++) {
            int c = wn + nj * 8 + tig * 2;
            float b0 = __ldg(&eb[c]), b1 = __ldg(&eb[c + 1]);
            if (r0 < M) *(float2*)(h + (size_t)r0 * H + c) = make_float2(acc[mt][nj][0] + b0, acc[mt][nj][1] + b1);
            if (r1 < M) *(float2*)(h + (size_t)r1 * H + c) = make_float2(acc[mt][nj][2] + b0, acc[mt][nj][3] + b1);
        }
    }
}

// ------- HMMA split-bf16 GEMM (round-13 version, bf16 Cl output) -----------
#define SMA_HI 0
#define SMA_LO 16384
#define SMW_HI 32768
#define SMW_LO 65536
#define SM_TOTAL 98304

__global__ void __launch_bounds__(256, 2) mma_gemm(
    const float* __restrict__ A,
    const __nv_bfloat16* __restrict__ wlh, const __nv_bfloat16* __restrict__ wll,
    const __nv_bfloat16* __restrict__ wrh, const __nv_bfloat16* __restrict__ wrl,
    __nv_bfloat16* __restrict__ Cl16, float* __restrict__ Cr, int M) {
    extern __shared__ char smem[];
    uint32_t sb = smem_to_u32(smem);
    int tid = threadIdx.x;
    int wid = tid >> 5, lane = tid & 31;
    int row0 = blockIdx.x * 64;

    const __nv_bfloat16* whi = (blockIdx.y == 0) ? wlh : wrh;
    const __nv_bfloat16* wlo = (blockIdx.y == 0) ? wll : wrl;

    const float4* A4 = (const float4*)(A + (size_t)row0 * H);
#pragma unroll
    for (int it = 0; it < 8; it++) {
        int g = tid + it * 256;
        int row = g >> 5;
        int k4 = g & 31;
        float4 v = make_float4(0.f, 0.f, 0.f, 0.f);
        if (row0 + row < M) v = A4[g];
        uint2 ph, pl;
        split_pack(v, ph, pl);
        uint32_t off = tile_off(row, k4 * 8);
        *(uint2*)(smem + SMA_HI + off) = ph;
        *(uint2*)(smem + SMA_LO + off) = pl;
    }
    const uint2* WH = (const uint2*)whi;
    const uint2* WL = (const uint2*)wlo;
#pragma unroll
    for (int it = 0; it < 16; it++) {
        int g = tid + it * 256;
        int row = g >> 5;
        uint32_t off = tile_off(row, (g & 31) * 8);
        *(uint2*)(smem + SMW_HI + off) = WH[g];
        *(uint2*)(smem + SMW_LO + off) = WL[g];
    }
    __syncthreads();

    int wm = (wid & 1) * 32;
    int wn = (wid >> 1) * 32;

    float acc[2][4][4];
#pragma unroll
    for (int mt = 0; mt < 2; mt++)
#pragma unroll
        for (int nj = 0; nj < 4; nj++)
#pragma unroll
            for (int i = 0; i < 4; i++) acc[mt][nj][i] = 0.f;

    int a_row_off = lane & 15;
    int a_kb_off = (lane >> 4) << 4;
    int b_row_off = (lane & 7) + ((lane >> 4) << 3);
    int b_kb_off = ((lane >> 3) & 1) << 4;

#pragma unroll
    for (int ks = 0; ks < 8; ks++) {
        int kb = ks * 32;
        uint32_t ah[2][4], al[2][4];
#pragma unroll
        for (int mt = 0; mt < 2; mt++) {
            int row = wm + mt * 16 + a_row_off;
            uint32_t off = tile_off(row, kb + a_kb_off);
            ldsm_x4(ah[mt], sb + SMA_HI + off);
            ldsm_x4(al[mt], sb + SMA_LO + off);
        }
        uint32_t bh[2][4], bl[2][4];
#pragma unroll
        for (int ng = 0; ng < 2; ng++) {
            int nrow = wn + ng * 16 + b_row_off;
            uint32_t off = tile_off(nrow, kb + b_kb_off);
            ldsm_x4(bh[ng], sb + SMW_HI + off);
            ldsm_x4(bl[ng], sb + SMW_LO + off);
        }
#pragma unroll
        for (int mt = 0; mt < 2; mt++) {
#pragma unroll
            for (int nj = 0; nj < 4; nj++) {
                int ng = nj >> 1, half = (nj & 1) * 2;
                mma_bf16(acc[mt][nj], ah[mt], bh[ng][half], bh[ng][half + 1]);
                mma_bf16(acc[mt][nj], ah[mt], bl[ng][half], bl[ng][half + 1]);
                mma_bf16(acc[mt][nj], al[mt], bh[ng][half], bh[ng][half + 1]);
            }
        }
    }

    int gid = lane >> 2, tig = lane & 3;
    if (blockIdx.y == 0) {
#pragma unroll
        for (int mt = 0; mt < 2; mt++) {
            int r0 = row0 + wm + mt * 16 + gid;
            int r1 = r0 + 8;
#pragma unroll
            for (int nj = 0; nj < 4; nj++) {
                int c = wn + nj * 8 + tig * 2;
                if (r0 < M) {
                    __nv_bfloat162 p = __float22bfloat162_rn(make_float2(acc[mt][nj][0], acc[mt][nj][1]));
                    *(__nv_bfloat162*)(Cl16 + (size_t)r0 * H + c) = p;
                }
                if (r1 < M) {
                    __nv_bfloat162 p = __float22bfloat162_rn(make_float2(acc[mt][nj][2], acc[mt][nj][3]));
                    *(__nv_bfloat162*)(Cl16 + (size_t)r1 * H + c) = p;
                }
            }
        }
    } else {
#pragma unroll
        for (int mt = 0; mt < 2; mt++) {
            int r0 = row0 + wm + mt * 16 + gid;
            int r1 = r0 + 8;
#pragma unroll
            for (int nj = 0; nj < 4; nj++) {
                int c = wn + nj * 8 + tig * 2;
                if (r0 < M) *(float2*)(Cr + (size_t)r0 * H + c) = make_float2(acc[mt][nj][0], acc[mt][nj][1]);
                if (r1 < M) *(float2*)(Cr + (size_t)r1 * H + c) = make_float2(acc[mt][nj][2], acc[mt][nj][3]);
            }
        }
    }
}

// ---------------- fused CSR build (all 4 layers) ----------------
__global__ void init_deg_kernel() {
    int i = blockIdx.x * blockDim.x + threadIdx.x;
    if (i < 4 * N_NODES) g_deg[i] = 1;
}

__global__ void hist_all_kernel(const int* __restrict__ e0, const int* __restrict__ e1,
                                const int* __restrict__ e2, const int* __restrict__ e3,
                                int E0, int E1, int E2, int E3) {
    int i = blockIdx.x * blockDim.x + threadIdx.x;
    const int* e; int E; int base;
    if (i < E0) { e = e0; E = E0; base = 0; }
    else { i -= E0;
        if (i < E1) { e = e1; E = E1; base = N_NODES; }
        else { i -= E1;
            if (i < E2) { e = e2; E = E2; base = 2 * N_NODES; }
            else { i -= E2; if (i >= E3) return; e = e3; E = E3; base = 3 * N_NODES; } } }
    atomicAdd(&g_deg[base + e[E + i]], 1);
}

__global__ void scan1_kernel() {
    __shared__ int shm[1024];
    int tid = threadIdx.x;
    int i = blockIdx.x * 1024 + tid;
    int v = (i < 4 * N_NODES) ? g_deg[i] : 0;
    shm[tid] = v;
    __syncthreads();
    for (int off = 1; off < 1024; off <<= 1) {
        int t = (tid >= off) ? shm[tid - off] : 0;
        __syncthreads();
        shm[tid] += t;
        __syncthreads();
    }
    if (i < 4 * N_NODES) g_rowptr[i] = shm[tid] - v;
    if (tid == 1023) g_bsum[blockIdx.x] = shm[1023];
}

__global__ void scan2_kernel(int nb) {
    __shared__ int shm[512];
    int tid = threadIdx.x;
    int v = (tid < nb) ? g_bsum[tid] : 0;
    shm[tid] = v;
    __syncthreads();
    for (int off = 1; off < 512; off <<= 1) {
        int t = (tid >= off) ? shm[tid - off] : 0;
        __syncthreads();
        shm[tid] += t;
        __syncthreads();
    }
    if (tid < nb) g_bsum[tid] = shm[tid] - v;
}

__global__ void scan3_kernel() {
    int i = blockIdx.x * blockDim.x + threadIdx.x;
    if (i >= 4 * N_NODES) return;
    int r = g_rowptr[i] + g_bsum[i >> 10];
    g_rowptr[i] = r;
    int layer = i / N_NODES;
    g_srcs[r] = i - layer * N_NODES;
    g_cursor[i] = r + 1;
}

__global__ void scatter_all_kernel(const int* __restrict__ e0, const int* __restrict__ e1,
                                   const int* __restrict__ e2, const int* __restrict__ e3,
                                   int E0, int E1, int E2, int E3) {
    int i = blockIdx.x * blockDim.x + threadIdx.x;
    const int* e; int E; int base;
    if (i < E0) { e = e0; E = E0; base = 0; }
    else { i -= E0;
        if (i < E1) { e = e1; E = E1; base = N_NODES; }
        else { i -= E1;
            if (i < E2) { e = e2; E = E2; base = 2 * N_NODES; }
            else { i -= E2; if (i >= E3) return; e = e3; E = E3; base = 3 * N_NODES; } } }
    int src = e[i];
    int dst = e[E + i];
    int pos = atomicAdd(&g_cursor[base + dst], 1);
    g_srcs[pos] = src;
}

// -- fused GATv2 softmax-aggregate (round-13 version, bf16 xl gathers) --
__device__ __forceinline__ float4 unpack_bf4(uint2 p) {
    float2 lo = __bfloat1622float2(*(__nv_bfloat162*)&p.x);
    float2 hi = __bfloat1622float2(*(__nv_bfloat162*)&p.y);
    return make_float4(lo.x, lo.y, hi.x, hi.y);
}

__global__ void gat_agg_kernel(const __nv_bfloat16* __restrict__ xl,
                               const float* __restrict__ xr,
                               const float* __restrict__ att, const float* __restrict__ bias,
                               float* __restrict__ hout, int layerBase) {
    int warp = (blockIdx.x * blockDim.x + threadIdx.x) >> 5;
    int lane = threadIdx.x & 31;
    if (warp >= N_NODES) return;
    int v = warp;
    bool odd = lane & 1;

    float4 xrv = __ldcs(((const float4*)(xr + (size_t)v * H)) + lane);
    float4 at = ((const float4*)att)[lane];
    float4 bv = ((const float4*)bias)[lane];

    int beg = g_rowptr[layerBase + v];
    int cnt = g_deg[layerBase + v];

    float m0 = -1e30f, s0 = 0.f, a0x = 0.f, a0y = 0.f, a0z = 0.f, a0w = 0.f;
    float m1 = -1e30f, s1 = 0.f, a1x = 0.f, a1y = 0.f, a1z = 0.f, a1w = 0.f;

    int c0 = __ldg(&g_srcs[beg]);
    int c1 = (cnt > 1) ? __ldg(&g_srcs[beg + 1]) : c0;
    uint2 pa = __ldg((const uint2*)(xl + (size_t)c0 * H) + lane);
    uint2 pb = __ldg((const uint2*)(xl + (size_t)c1 * H) + lane);

    for (int j = 0; j < cnt; j += 2) {
        int n0 = (j + 2 < cnt) ? __ldg(&g_srcs[beg + j + 2]) : c0;
        int n1 = (j + 3 < cnt) ? __ldg(&g_srcs[beg + j + 3]) : n0;
        uint2 npa = __ldg((const uint2*)(xl + (size_t)n0 * H) + lane);
        uint2 npb = __ldg((const uint2*)(xl + (size_t)n1 * H) + lane);

        float4 a = unpack_bf4(pa);
        float4 b = unpack_bf4(pb);

        bool has1 = (j + 1) < cnt;
        float tx0 = a.x + xrv.x, ty0 = a.y + xrv.y, tz0 = a.z + xrv.z, tw0 = a.w + xrv.w;
        float tx1 = b.x + xrv.x, ty1 = b.y + xrv.y, tz1 = b.z + xrv.z, tw1 = b.w + xrv.w;
        tx0 = fmaxf(tx0, 0.f) + NEG_SLOPE * fminf(tx0, 0.f);
        ty0 = fmaxf(ty0, 0.f) + NEG_SLOPE * fminf(ty0, 0.f);
        tz0 = fmaxf(tz0, 0.f) + NEG_SLOPE * fminf(tz0, 0.f);
        tw0 = fmaxf(tw0, 0.f) + NEG_SLOPE * fminf(tw0, 0.f);
        tx1 = fmaxf(tx1, 0.f) + NEG_SLOPE * fminf(tx1, 0.f);
        ty1 = fmaxf(ty1, 0.f) + NEG_SLOPE * fminf(ty1, 0.f);
        tz1 = fmaxf(tz1, 0.f) + NEG_SLOPE * fminf(tz1, 0.f);
        tw1 = fmaxf(tw1, 0.f) + NEG_SLOPE * fminf(tw1, 0.f);
        float d0 = tx0 * at.x + ty0 * at.y + tz0 * at.z + tw0 * at.w;
        float d1 = tx1 * at.x + ty1 * at.y + tz1 * at.z + tw1 * at.w;

        float send = odd ? d0 : d1;
        float recv = __shfl_xor_sync(0xffffffffu, send, 1);
        float s = odd ? (d1 + recv) : (d0 + recv);
#pragma unroll
        for (int off = 2; off < 32; off <<= 1)
            s += __shfl_xor_sync(0xffffffffu, s, off);
        float t = __shfl_xor_sync(0xffffffffu, s, 1);
        d0 = odd ? t : s;
        d1 = odd ? s : t;

        {
            float nm = fmaxf(m0, d0);
            float sc = __expf(m0 - nm);
            float ex = __expf(d0 - nm);
            s0 = s0 * sc + ex;
            a0x = a0x * sc + ex * a.x;
            a0y = a0y * sc + ex * a.y;
            a0z = a0z * sc + ex * a.z;
            a0w = a0w * sc + ex * a.w;
            m0 = nm;
        }
        if (has1) {
            float nm = fmaxf(m1, d1);
            float sc = __expf(m1 - nm);
            float ex = __expf(d1 - nm);
            s1 = s1 * sc + ex;
            a1x = a1x * sc + ex * b.x;
            a1y = a1y * sc + ex * b.y;
            a1z = a1z * sc + ex * b.z;
            a1w = a1w * sc + ex * b.w;
            m1 = nm;
        }
        pa = npa; pb = npb;
    }

    float nm = fmaxf(m0, m1);
    float sc0 = __expf(m0 - nm);
    float sc1 = __expf(m1 - nm);
    float s = s0 * sc0 + s1 * sc1;
    float inv = 1.f / s;
    float4 o;
    o.x = (a0x * sc0 + a1x * sc1) * inv + bv.x;
    o.y = (a0y * sc0 + a1y * sc1) * inv + bv.y;
    o.z = (a0z * sc0 + a1z * sc1) * inv + bv.z;
    o.w = (a0w * sc0 + a1w * sc1) * inv + bv.w;
    __stcs(((float4*)(hout + (size_t)v * H)) + lane, o);
}

// ---------------- pooling (atomic-free 2-stage) + output head --------------
__global__ void pool1_kernel(const float* __restrict__ h, const int* __restrict__ ground,
                             const int* __restrict__ batch, int ng) {
    __shared__ float acc[NG * H];
    int tid = threadIdx.x;
    for (int i = tid; i < NG * H; i += 128) acc[i] = 0.f;
    __syncthreads();
    for (int g = blockIdx.x; g < ng; g += POOL_BLKS) {
        int v = ground[g];
        int b = batch[g];
        acc[b * H + tid] += h[(size_t)v * H + tid];
    }
    __syncthreads();
    float* part = g_part + (size_t)blockIdx.x * NG * H;
    for (int i = tid; i < NG * H; i += 128) part[i] = acc[i];
}

__global__ void pool2_kernel() {
    int i = blockIdx.x * blockDim.x + threadIdx.x;   // 8192 total
    if (i >= NG * H) return;
    float s = 0.f;
#pragma unroll 4
    for (int p = 0; p < POOL_BLKS; p++) s += g_part[(size_t)p * NG * H + i];
    g_pooled[i] = s;
}

__global__ void final_kernel(const float* __restrict__ W, const float* __restrict__ b,
                             float* __restrict__ out) {
    int g = blockIdx.x;
    int o = threadIdx.x;
    float acc = b[o];
#pragma unroll
    for (int k = 0; k < H; k++) acc += g_pooled[g * H + k] * W[k * F_OUT + o];
    out[g * F_OUT + o] = acc;
}

// ---------------- launch ----------------
extern "C" void kernel_launch(void* const* d_in, const int* in_sizes, int n_in,
                              void* d_out, int out_size) {
    const float* x      = (const float*)d_in[0];
    const int*   e0     = (const int*)d_in[1];
    const int*   e2     = (const int*)d_in[2];
    const int*   e1     = (const int*)d_in[3];
    const int*   e3     = (const int*)d_in[4];
    const int*   ground = (const int*)d_in[5];
    const int*   batch  = (const int*)d_in[7];
    const float* embW   = (const float*)d_in[8];
    const float* embb   = (const float*)d_in[9];
    const float* Wl     = (const float*)d_in[10];
    const float* Wr     = (const float*)d_in[11];
    const float* att    = (const float*)d_in[12];
    const float* bias   = (const float*)d_in[13];
    const float* outW   = (const float*)d_in[14];
    const float* outb   = (const float*)d_in[15];
    int ng = in_sizes[5];

    int E0 = in_sizes[1] / 2, E1 = in_sizes[3] / 2, E2 = in_sizes[2] / 2, E3 = in_sizes[4] / 2;
    int Etot = E0 + E1 + E2 + E3;

    float *hA, *hB, *xrp;
    __nv_bfloat16 *xlp, *wh, *wl;
    cudaGetSymbolAddress((void**)&hA, g_hA);
    cudaGetSymbolAddress((void**)&hB, g_hB);
    cudaGetSymbolAddress((void**)&xlp, g_xl);
    cudaGetSymbolAddress((void**)&xrp, g_xr);
    cudaGetSymbolAddress((void**)&wh, g_wh);
    cudaGetSymbolAddress((void**)&wl, g_wl);

    cudaFuncSetAttribute(mma_gemm, cudaFuncAttributeMaxDynamicSharedMemorySize, SM_TOTAL);

    static cudaStream_t s2 = nullptr;
    static cudaEvent_t evFork = nullptr, evJoin = nullptr;
    if (!s2) {
        cudaStreamCreateWithFlags(&s2, cudaStreamNonBlocking);
        cudaEventCreateWithFlags(&evFork, cudaEventDisableTiming);
        cudaEventCreateWithFlags(&evJoin, cudaEventDisableTiming);
    }

    // ---- fork: CSR build chain on side stream ----
    cudaEventRecord(evFork, 0);
    cudaStreamWaitEvent(s2, evFork, 0);

    int scanBlocks = (4 * N_NODES + 1023) / 1024;
    init_deg_kernel<<<(4 * N_NODES + 255) / 256, 256, 0, s2>>>();
    hist_all_kernel<<<(Etot + 255) / 256, 256, 0, s2>>>(e0, e1, e2, e3, E0, E1, E2, E3);
    scan1_kernel<<<scanBlocks, 1024, 0, s2>>>();
    scan2_kernel<<<1, 512, 0, s2>>>(scanBlocks);
    scan3_kernel<<<(4 * N_NODES + 255) / 256, 256, 0, s2>>>();
    scatter_all_kernel<<<(Etot + 255) / 256, 256, 0, s2>>>(e0, e1, e2, e3, E0, E1, E2, E3);
    cudaEventRecord(evJoin, s2);

    // ---- main stream: wprep -> emb(MMA) -> gemm0 ----
    wprep_emb_kernel<<<(H * F_IN + 255) / 256, 256>>>(embW);
    wprep_kernel<<<(8 * H * H + 255) / 256, 256>>>(Wl, Wr);
    emb_mma<<<(N_NODES + 63) / 64, 256, ESM_TOTAL>>>(x, embb, hA, N_NODES);

    dim3 ggrid((N_NODES + 63) / 64, 2);
    float* hin = hA;
    float* hout = hB;

    mma_gemm<<<ggrid, 256, SM_TOTAL>>>(hin, wh, wl, wh + H * H, wl + H * H, xlp, xrp, N_NODES);

    cudaStreamWaitEvent(0, evJoin, 0);

    for (int l = 0; l < 4; l++) {
        if (l > 0) {
            mma_gemm<<<ggrid, 256, SM_TOTAL>>>(hin, wh + (2 * l) * H * H, wl + (2 * l) * H * H,
                                               wh + (2 * l + 1) * H * H, wl + (2 * l + 1) * H * H,
                                               xlp, xrp, N_NODES);
        }
        gat_agg_kernel<<<(N_NODES * 32 + 255) / 256, 256>>>(
            xlp, xrp, att + l * H, bias + l * H, hout, l * N_NODES);
        float* t = hin; hin = hout; hout = t;
    }

    pool1_kernel<<<POOL_BLKS, 128>>>(hin, ground, batch, ng);
    pool2_kernel<<<(NG * H + 255) / 256, 256>>>();
    final_kernel<<<NG, F_OUT>>>(outW, outb, (float*)d_out);
}

// round 15
// speedup vs baseline: 1.2615x; 1.0097x over previous
#include <cuda_runtime.h>
#include <cuda_bf16.h>
#include <cstdint>

#define N_NODES 100000
#define H 128
#define F_IN 32
#define F_OUT 16
#define NG 64
#define NEG_SLOPE 0.2f
#define SRC_MAX 2800000
#define POOL_BLKS 128

// ---------------- device scratch ----------------
__device__ float g_hA[N_NODES * H];
__device__ float g_hB[N_NODES * H];
__device__ __nv_bfloat16 g_xl[N_NODES * H];
__device__ float g_xr[N_NODES * H];
__device__ int   g_deg[4 * N_NODES];
__device__ int   g_rowptr[4 * N_NODES];
__device__ int   g_cursor[4 * N_NODES];
__device__ int   g_srcs[SRC_MAX];
__device__ int   g_bsum[512];
__device__ float g_pooled[NG * H];
__device__ float g_part[POOL_BLKS * NG * H];
__device__ __nv_bfloat16 g_wh[8 * H * H];
__device__ __nv_bfloat16 g_wl[8 * H * H];
__device__ __nv_bfloat16 g_ewh[H * F_IN];
__device__ __nv_bfloat16 g_ewl[H * F_IN];

// ---------------- mma.sync helpers ----------------
__device__ __forceinline__ uint32_t smem_to_u32(const void* p) {
    uint32_t a;
    asm("{ .reg .u64 t; cvta.to.shared.u64 t, %1; cvt.u32.u64 %0, t; }" : "=r"(a) : "l"(p));
    return a;
}
__device__ __forceinline__ void ldsm_x4(uint32_t r[4], uint32_t addr) {
    asm volatile("ldmatrix.sync.aligned.m8n8.x4.shared.b16 {%0,%1,%2,%3}, [%4];"
                 : "=r"(r[0]), "=r"(r[1]), "=r"(r[2]), "=r"(r[3]) : "r"(addr));
}
__device__ __forceinline__ void mma_bf16(float c[4], const uint32_t a[4],
                                         uint32_t b0, uint32_t b1) {
    asm volatile(
        "mma.sync.aligned.m16n8k16.row.col.f32.bf16.bf16.f32 "
        "{%0,%1,%2,%3}, {%4,%5,%6,%7}, {%8,%9}, {%0,%1,%2,%3};"
        : "+f"(c[0]), "+f"(c[1]), "+f"(c[2]), "+f"(c[3])
        : "r"(a[0]), "r"(a[1]), "r"(a[2]), "r"(a[3]), "r"(b0), "r"(b1));
}

__device__ __forceinline__ uint32_t tile_off(int row, int kb) {
    return (uint32_t)(row * 256) + (uint32_t)(kb ^ ((row & 7) << 4));
}
__device__ __forceinline__ uint32_t tile_off128(int row, int kb) {
    return (uint32_t)(row * 128) + (uint32_t)(kb ^ ((row & 7) << 4));
}

__device__ __forceinline__ void split_pack(float4 v, uint2& ph, uint2& pl) {
    __nv_bfloat16 h0 = __float2bfloat16(v.x);
    __nv_bfloat16 h1 = __float2bfloat16(v.y);
    __nv_bfloat16 h2 = __float2bfloat16(v.z);
    __nv_bfloat16 h3 = __float2bfloat16(v.w);
    __nv_bfloat16 l0 = __float2bfloat16(v.x - __bfloat162float(h0));
    __nv_bfloat16 l1 = __float2bfloat16(v.y - __bfloat162float(h1));
    __nv_bfloat16 l2 = __float2bfloat16(v.z - __bfloat162float(h2));
    __nv_bfloat16 l3 = __float2bfloat16(v.w - __bfloat162float(h3));
    ph.x = (uint32_t)__bfloat16_as_ushort(h0) | ((uint32_t)__bfloat16_as_ushort(h1) << 16);
    ph.y = (uint32_t)__bfloat16_as_ushort(h2) | ((uint32_t)__bfloat16_as_ushort(h3) << 16);
    pl.x = (uint32_t)__bfloat16_as_ushort(l0) | ((uint32_t)__bfloat16_as_ushort(l1) << 16);
    pl.y = (uint32_t)__bfloat16_as_ushort(l2) | ((uint32_t)__bfloat16_as_ushort(l3) << 16);
}

// ---------------- fused weight prep (main + emb) ----------------
__global__ void wprep_all_kernel(const float* __restrict__ Wl, const float* __restrict__ Wr,
                                 const float* __restrict__ We) {
    int idx = blockIdx.x * 256 + threadIdx.x;
    if (idx < 8 * H * H) {
        int mat = idx >> 14;
        int e = idx & 16383;
        int n = e >> 7, k = e & 127;
        int layer = mat >> 1;
        const float* W = ((mat & 1) ? Wr : Wl) + layer * H * H;
        float v = W[k * H + n];
        __nv_bfloat16 hi = __float2bfloat16(v);
        g_wh[idx] = hi;
        g_wl[idx] = __float2bfloat16(v - __bfloat162float(hi));
    } else {
        int j = idx - 8 * H * H;
        if (j >= H * F_IN) return;
        int n = j >> 5, k = j & 31;
        float v = We[k * H + n];
        __nv_bfloat16 hi = __float2bfloat16(v);
        g_ewh[j] = hi;
        g_ewl[j] = __float2bfloat16(v - __bfloat162float(hi));
    }
}

// ---------------- emb via HMMA ----------------
#define ESA_HI 0
#define ESA_LO 8192
#define ESW_HI 16384
#define ESW_LO 32768
#define ESM_TOTAL 49152

__global__ void __launch_bounds__(256, 2) emb_mma(
    const float* __restrict__ x, const float* __restrict__ eb,
    float* __restrict__ h, int M) {
    extern __shared__ char smem[];
    uint32_t sb = smem_to_u32(smem);
    int tid = threadIdx.x;
    int wid = tid >> 5, lane = tid & 31;
    int row0 = blockIdx.x * 64;

    const float4* X4 = (const float4*)(x + (size_t)row0 * F_IN);
#pragma unroll
    for (int it = 0; it < 2; it++) {
        int g = tid + it * 256;
        int row = g >> 3;
        int k4 = g & 7;
        float4 v = make_float4(0.f, 0.f, 0.f, 0.f);
        if (row0 + row < M) v = X4[g];
        uint2 ph, pl;
        split_pack(v, ph, pl);
        uint32_t off = tile_off128(row, k4 * 8);
        *(uint2*)(smem + ESA_HI + off) = ph;
        *(uint2*)(smem + ESA_LO + off) = pl;
    }
    const uint2* WH = (const uint2*)g_ewh;
    const uint2* WL = (const uint2*)g_ewl;
#pragma unroll
    for (int it = 0; it < 4; it++) {
        int g = tid + it * 256;
        int row = g >> 3;
        uint32_t off = tile_off128(row, (g & 7) * 8);
        *(uint2*)(smem + ESW_HI + off) = WH[g];
        *(uint2*)(smem + ESW_LO + off) = WL[g];
    }
    __syncthreads();

    int wm = (wid & 1) * 32;
    int wn = (wid >> 1) * 32;

    float acc[2][4][4];
#pragma unroll
    for (int mt = 0; mt < 2; mt++)
#pragma unroll
        for (int nj = 0; nj < 4; nj++)
#pragma unroll
            for (int i = 0; i < 4; i++) acc[mt][nj][i] = 0.f;

    int a_row_off = lane & 15;
    int a_kb_off = (lane >> 4) << 4;
    int b_row_off = (lane & 7) + ((lane >> 4) << 3);
    int b_kb_off = ((lane >> 3) & 1) << 4;

#pragma unroll
    for (int ks = 0; ks < 2; ks++) {
        int kb = ks * 32;
        uint32_t ah[2][4], al[2][4];
#pragma unroll
        for (int mt = 0; mt < 2; mt++) {
            int row = wm + mt * 16 + a_row_off;
            uint32_t off = tile_off128(row, kb + a_kb_off);
            ldsm_x4(ah[mt], sb + ESA_HI + off);
            ldsm_x4(al[mt], sb + ESA_LO + off);
        }
        uint32_t bh[2][4], bl[2][4];
#pragma unroll
        for (int ng = 0; ng < 2; ng++) {
            int nrow = wn + ng * 16 + b_row_off;
            uint32_t off = tile_off128(nrow, kb + b_kb_off);
            ldsm_x4(bh[ng], sb + ESW_HI + off);
            ldsm_x4(bl[ng], sb + ESW_LO + off);
        }
#pragma unroll
        for (int mt = 0; mt < 2; mt++) {
#pragma unroll
            for (int nj = 0; nj < 4; nj++) {
                int ng = nj >> 1, half = (nj & 1) * 2;
                mma_bf16(acc[mt][nj], ah[mt], bh[ng][half], bh[ng][half + 1]);
                mma_bf16(acc[mt][nj], ah[mt], bl[ng][half], bl[ng][half + 1]);
                mma_bf16(acc[mt][nj], al[mt], bh[ng][half], bh[ng][half + 1]);
            }
        }
    }

    int gid = lane >> 2, tig = lane & 3;
#pragma unroll
    for (int mt = 0; mt < 2; mt++) {
        int r0 = row0 + wm + mt * 16 + gid;
        int r1 = r0 + 8;
#pragma unroll
        for (int nj = 0; nj < 4; nj++) {
            int c = wn + nj * 8 + tig * 2;
            float b0 = __ldg(&eb[c]), b1 = __ldg(&eb[c + 1]);
            if (r0 < M) *(float2*)(h + (size_t)r0 * H + c) = make_float2(acc[mt][nj][0] + b0, acc[mt][nj][1] + b1);
            if (r1 < M) *(float2*)(h + (size_t)r1 * H + c) = make_float2(acc[mt][nj][2] + b0, acc[mt][nj][3] + b1);
        }
    }
}

// ------- HMMA split-bf16 GEMM (bf16 Cl output) ------------------------------
#define SMA_HI 0
#define SMA_LO 16384
#define SMW_HI 32768
#define SMW_LO 65536
#define SM_TOTAL 98304

__global__ void __launch_bounds__(256, 2) mma_gemm(
    const float* __restrict__ A,
    const __nv_bfloat16* __restrict__ wlh, const __nv_bfloat16* __restrict__ wll,
    const __nv_bfloat16* __restrict__ wrh, const __nv_bfloat16* __restrict__ wrl,
    __nv_bfloat16* __restrict__ Cl16, float* __restrict__ Cr, int M) {
    extern __shared__ char smem[];
    uint32_t sb = smem_to_u32(smem);
    int tid = threadIdx.x;
    int wid = tid >> 5, lane = tid & 31;
    int row0 = blockIdx.x * 64;

    const __nv_bfloat16* whi = (blockIdx.y == 0) ? wlh : wrh;
    const __nv_bfloat16* wlo = (blockIdx.y == 0) ? wll : wrl;

    const float4* A4 = (const float4*)(A + (size_t)row0 * H);
#pragma unroll
    for (int it = 0; it < 8; it++) {
        int g = tid + it * 256;
        int row = g >> 5;
        int k4 = g & 31;
        float4 v = make_float4(0.f, 0.f, 0.f, 0.f);
        if (row0 + row < M) v = A4[g];
        uint2 ph, pl;
        split_pack(v, ph, pl);
        uint32_t off = tile_off(row, k4 * 8);
        *(uint2*)(smem + SMA_HI + off) = ph;
        *(uint2*)(smem + SMA_LO + off) = pl;
    }
    const uint2* WH = (const uint2*)whi;
    const uint2* WL = (const uint2*)wlo;
#pragma unroll
    for (int it = 0; it < 16; it++) {
        int g = tid + it * 256;
        int row = g >> 5;
        uint32_t off = tile_off(row, (g & 31) * 8);
        *(uint2*)(smem + SMW_HI + off) = WH[g];
        *(uint2*)(smem + SMW_LO + off) = WL[g];
    }
    __syncthreads();

    int wm = (wid & 1) * 32;
    int wn = (wid >> 1) * 32;

    float acc[2][4][4];
#pragma unroll
    for (int mt = 0; mt < 2; mt++)
#pragma unroll
        for (int nj = 0; nj < 4; nj++)
#pragma unroll
            for (int i = 0; i < 4; i++) acc[mt][nj][i] = 0.f;

    int a_row_off = lane & 15;
    int a_kb_off = (lane >> 4) << 4;
    int b_row_off = (lane & 7) + ((lane >> 4) << 3);
    int b_kb_off = ((lane >> 3) & 1) << 4;

#pragma unroll
    for (int ks = 0; ks < 8; ks++) {
        int kb = ks * 32;
        uint32_t ah[2][4], al[2][4];
#pragma unroll
        for (int mt = 0; mt < 2; mt++) {
            int row = wm + mt * 16 + a_row_off;
            uint32_t off = tile_off(row, kb + a_kb_off);
            ldsm_x4(ah[mt], sb + SMA_HI + off);
            ldsm_x4(al[mt], sb + SMA_LO + off);
        }
        uint32_t bh[2][4], bl[2][4];
#pragma unroll
        for (int ng = 0; ng < 2; ng++) {
            int nrow = wn + ng * 16 + b_row_off;
            uint32_t off = tile_off(nrow, kb + b_kb_off);
            ldsm_x4(bh[ng], sb + SMW_HI + off);
            ldsm_x4(bl[ng], sb + SMW_LO + off);
        }
#pragma unroll
        for (int mt = 0; mt < 2; mt++) {
#pragma unroll
            for (int nj = 0; nj < 4; nj++) {
                int ng = nj >> 1, half = (nj & 1) * 2;
                mma_bf16(acc[mt][nj], ah[mt], bh[ng][half], bh[ng][half + 1]);
                mma_bf16(acc[mt][nj], ah[mt], bl[ng][half], bl[ng][half + 1]);
                mma_bf16(acc[mt][nj], al[mt], bh[ng][half], bh[ng][half + 1]);
            }
        }
    }

    int gid = lane >> 2, tig = lane & 3;
    if (blockIdx.y == 0) {
#pragma unroll
        for (int mt = 0; mt < 2; mt++) {
            int r0 = row0 + wm + mt * 16 + gid;
            int r1 = r0 + 8;
#pragma unroll
            for (int nj = 0; nj < 4; nj++) {
                int c = wn + nj * 8 + tig * 2;
                if (r0 < M) {
                    __nv_bfloat162 p = __float22bfloat162_rn(make_float2(acc[mt][nj][0], acc[mt][nj][1]));
                    *(__nv_bfloat162*)(Cl16 + (size_t)r0 * H + c) = p;
                }
                if (r1 < M) {
                    __nv_bfloat162 p = __float22bfloat162_rn(make_float2(acc[mt][nj][2], acc[mt][nj][3]));
                    *(__nv_bfloat162*)(Cl16 + (size_t)r1 * H + c) = p;
                }
            }
        }
    } else {
#pragma unroll
        for (int mt = 0; mt < 2; mt++) {
            int r0 = row0 + wm + mt * 16 + gid;
            int r1 = r0 + 8;
#pragma unroll
            for (int nj = 0; nj < 4; nj++) {
                int c = wn + nj * 8 + tig * 2;
                if (r0 < M) *(float2*)(Cr + (size_t)r0 * H + c) = make_float2(acc[mt][nj][0], acc[mt][nj][1]);
                if (r1 < M) *(float2*)(Cr + (size_t)r1 * H + c) = make_float2(acc[mt][nj][2], acc[mt][nj][3]);
            }
        }
    }
}

// ---------------- per-layer CSR build ----------------
__global__ void init_deg_layer(int lbase) {
    int i = blockIdx.x * blockDim.x + threadIdx.x;
    if (i < N_NODES) g_deg[lbase + i] = 1;
}

__global__ void hist_layer(const int* __restrict__ e, int E, int lbase) {
    int i = blockIdx.x * blockDim.x + threadIdx.x;
    if (i >= E) return;
    atomicAdd(&g_deg[lbase + e[E + i]], 1);
}

__global__ void scan1_layer(int lbase) {
    __shared__ int shm[1024];
    int tid = threadIdx.x;
    int i = blockIdx.x * 1024 + tid;
    int v = (i < N_NODES) ? g_deg[lbase + i] : 0;
    shm[tid] = v;
    __syncthreads();
    for (int off = 1; off < 1024; off <<= 1) {
        int t = (tid >= off) ? shm[tid - off] : 0;
        __syncthreads();
        shm[tid] += t;
        __syncthreads();
    }
    if (i < N_NODES) g_rowptr[lbase + i] = shm[tid] - v;
    if (tid == 1023) g_bsum[blockIdx.x] = shm[1023];
}

__global__ void scan2_kernel(int nb) {
    __shared__ int shm[512];
    int tid = threadIdx.x;
    int v = (tid < nb) ? g_bsum[tid] : 0;
    shm[tid] = v;
    __syncthreads();
    for (int off = 1; off < 512; off <<= 1) {
        int t = (tid >= off) ? shm[tid - off] : 0;
        __syncthreads();
        shm[tid] += t;
        __syncthreads();
    }
    if (tid < nb) g_bsum[tid] = shm[tid] - v;
}

__global__ void scan3_layer(int lbase, int srcBase) {
    int i = blockIdx.x * blockDim.x + threadIdx.x;
    if (i >= N_NODES) return;
    int r = g_rowptr[lbase + i] + g_bsum[i >> 10] + srcBase;
    g_rowptr[lbase + i] = r;
    g_srcs[r] = i;           // self loop first
    g_cursor[lbase + i] = r + 1;
}

__global__ void scatter_layer(const int* __restrict__ e, int E, int lbase) {
    int i = blockIdx.x * blockDim.x + threadIdx.x;
    if (i >= E) return;
    int src = e[i];
    int dst = e[E + i];
    int pos = atomicAdd(&g_cursor[lbase + dst], 1);
    g_srcs[pos] = src;
}

// -- fused GATv2 softmax-aggregate (bf16 xl gathers) --
__device__ __forceinline__ float4 unpack_bf4(uint2 p) {
    float2 lo = __bfloat1622float2(*(__nv_bfloat162*)&p.x);
    float2 hi = __bfloat1622float2(*(__nv_bfloat162*)&p.y);
    return make_float4(lo.x, lo.y, hi.x, hi.y);
}

__global__ void gat_agg_kernel(const __nv_bfloat16* __restrict__ xl,
                               const float* __restrict__ xr,
                               const float* __restrict__ att, const float* __restrict__ bias,
                               float* __restrict__ hout, int layerBase) {
    int warp = (blockIdx.x * blockDim.x + threadIdx.x) >> 5;
    int lane = threadIdx.x & 31;
    if (warp >= N_NODES) return;
    int v = warp;
    bool odd = lane & 1;

    float4 xrv = __ldcs(((const float4*)(xr + (size_t)v * H)) + lane);
    float4 at = ((const float4*)att)[lane];
    float4 bv = ((const float4*)bias)[lane];

    int beg = g_rowptr[layerBase + v];
    int cnt = g_deg[layerBase + v];

    float m0 = -1e30f, s0 = 0.f, a0x = 0.f, a0y = 0.f, a0z = 0.f, a0w = 0.f;
    float m1 = -1e30f, s1 = 0.f, a1x = 0.f, a1y = 0.f, a1z = 0.f, a1w = 0.f;

    int c0 = __ldg(&g_srcs[beg]);
    int c1 = (cnt > 1) ? __ldg(&g_srcs[beg + 1]) : c0;
    uint2 pa = __ldg((const uint2*)(xl + (size_t)c0 * H) + lane);
    uint2 pb = __ldg((const uint2*)(xl + (size_t)c1 * H) + lane);

    for (int j = 0; j < cnt; j += 2) {
        int n0 = (j + 2 < cnt) ? __ldg(&g_srcs[beg + j + 2]) : c0;
        int n1 = (j + 3 < cnt) ? __ldg(&g_srcs[beg + j + 3]) : n0;
        uint2 npa = __ldg((const uint2*)(xl + (size_t)n0 * H) + lane);
        uint2 npb = __ldg((const uint2*)(xl + (size_t)n1 * H) + lane);

        float4 a = unpack_bf4(pa);
        float4 b = unpack_bf4(pb);

        bool has1 = (j + 1) < cnt;
        float tx0 = a.x + xrv.x, ty0 = a.y + xrv.y, tz0 = a.z + xrv.z, tw0 = a.w + xrv.w;
        float tx1 = b.x + xrv.x, ty1 = b.y + xrv.y, tz1 = b.z + xrv.z, tw1 = b.w + xrv.w;
        tx0 = fmaxf(tx0, 0.f) + NEG_SLOPE * fminf(tx0, 0.f);
        ty0 = fmaxf(ty0, 0.f) + NEG_SLOPE * fminf(ty0, 0.f);
        tz0 = fmaxf(tz0, 0.f) + NEG_SLOPE * fminf(tz0, 0.f);
        tw0 = fmaxf(tw0, 0.f) + NEG_SLOPE * fminf(tw0, 0.f);
        tx1 = fmaxf(tx1, 0.f) + NEG_SLOPE * fminf(tx1, 0.f);
        ty1 = fmaxf(ty1, 0.f) + NEG_SLOPE * fminf(ty1, 0.f);
        tz1 = fmaxf(tz1, 0.f) + NEG_SLOPE * fminf(tz1, 0.f);
        tw1 = fmaxf(tw1, 0.f) + NEG_SLOPE * fminf(tw1, 0.f);
        float d0 = tx0 * at.x + ty0 * at.y + tz0 * at.z + tw0 * at.w;
        float d1 = tx1 * at.x + ty1 * at.y + tz1 * at.z + tw1 * at.w;

        float send = odd ? d0 : d1;
        float recv = __shfl_xor_sync(0xffffffffu, send, 1);
        float s = odd ? (d1 + recv) : (d0 + recv);
#pragma unroll
        for (int off = 2; off < 32; off <<= 1)
            s += __shfl_xor_sync(0xffffffffu, s, off);
        float t = __shfl_xor_sync(0xffffffffu, s, 1);
        d0 = odd ? t : s;
        d1 = odd ? s : t;

        {
            float nm = fmaxf(m0, d0);
            float sc = __expf(m0 - nm);
            float ex = __expf(d0 - nm);
            s0 = s0 * sc + ex;
            a0x = a0x * sc + ex * a.x;
            a0y = a0y * sc + ex * a.y;
            a0z = a0z * sc + ex * a.z;
            a0w = a0w * sc + ex * a.w;
            m0 = nm;
        }
        if (has1) {
            float nm = fmaxf(m1, d1);
            float sc = __expf(m1 - nm);
            float ex = __expf(d1 - nm);
            s1 = s1 * sc + ex;
            a1x = a1x * sc + ex * b.x;
            a1y = a1y * sc + ex * b.y;
            a1z = a1z * sc + ex * b.z;
            a1w = a1w * sc + ex * b.w;
            m1 = nm;
        }
        pa = npa; pb = npb;
    }

    float nm = fmaxf(m0, m1);
    float sc0 = __expf(m0 - nm);
    float sc1 = __expf(m1 - nm);
    float s = s0 * sc0 + s1 * sc1;
    float inv = 1.f / s;
    float4 o;
    o.x = (a0x * sc0 + a1x * sc1) * inv + bv.x;
    o.y = (a0y * sc0 + a1y * sc1) * inv + bv.y;
    o.z = (a0z * sc0 + a1z * sc1) * inv + bv.z;
    o.w = (a0w * sc0 + a1w * sc1) * inv + bv.w;
    __stcs(((float4*)(hout + (size_t)v * H)) + lane, o);
}

// ---------------- pooling (atomic-free 2-stage) + output head --------------
__global__ void pool1_kernel(const float* __restrict__ h, const int* __restrict__ ground,
                             const int* __restrict__ batch, int ng) {
    __shared__ float acc[NG * H];
    int tid = threadIdx.x;
    for (int i = tid; i < NG * H; i += 128) acc[i] = 0.f;
    __syncthreads();
    for (int g = blockIdx.x; g < ng; g += POOL_BLKS) {
        int v = ground[g];
        int b = batch[g];
        acc[b * H + tid] += h[(size_t)v * H + tid];
    }
    __syncthreads();
    float* part = g_part + (size_t)blockIdx.x * NG * H;
    for (int i = tid; i < NG * H; i += 128) part[i] = acc[i];
}

__global__ void pool2_kernel() {
    int i = blockIdx.x * blockDim.x + threadIdx.x;
    if (i >= NG * H) return;
    float s = 0.f;
#pragma unroll 4
    for (int p = 0; p < POOL_BLKS; p++) s += g_part[(size_t)p * NG * H + i];
    g_pooled[i] = s;
}

__global__ void final_kernel(const float* __restrict__ W, const float* __restrict__ b,
                             float* __restrict__ out) {
    int g = blockIdx.x;
    int o = threadIdx.x;
    float acc = b[o];
#pragma unroll
    for (int k = 0; k < H; k++) acc += g_pooled[g * H + k] * W[k * F_OUT + o];
    out[g * F_OUT + o] = acc;
}

// ---------------- launch ----------------
extern "C" void kernel_launch(void* const* d_in, const int* in_sizes, int n_in,
                              void* d_out, int out_size) {
    const float* x      = (const float*)d_in[0];
    const int*   e0     = (const int*)d_in[1];
    const int*   e2     = (const int*)d_in[2];
    const int*   e1     = (const int*)d_in[3];
    const int*   e3     = (const int*)d_in[4];
    const int*   ground = (const int*)d_in[5];
    const int*   batch  = (const int*)d_in[7];
    const float* embW   = (const float*)d_in[8];
    const float* embb   = (const float*)d_in[9];
    const float* Wl     = (const float*)d_in[10];
    const float* Wr     = (const float*)d_in[11];
    const float* att    = (const float*)d_in[12];
    const float* bias   = (const float*)d_in[13];
    const float* outW   = (const float*)d_in[14];
    const float* outb   = (const float*)d_in[15];
    int ng = in_sizes[5];

    int Es[4] = {in_sizes[1] / 2, in_sizes[3] / 2, in_sizes[2] / 2, in_sizes[4] / 2};
    const int* eis[4] = {e0, e1, e2, e3};

    float *hA, *hB, *xrp;
    __nv_bfloat16 *xlp, *wh, *wl;
    cudaGetSymbolAddress((void**)&hA, g_hA);
    cudaGetSymbolAddress((void**)&hB, g_hB);
    cudaGetSymbolAddress((void**)&xlp, g_xl);
    cudaGetSymbolAddress((void**)&xrp, g_xr);
    cudaGetSymbolAddress((void**)&wh, g_wh);
    cudaGetSymbolAddress((void**)&wl, g_wl);

    cudaFuncSetAttribute(mma_gemm, cudaFuncAttributeMaxDynamicSharedMemorySize, SM_TOTAL);

    static cudaStream_t s2 = nullptr;
    static cudaEvent_t evFork = nullptr;
    static cudaEvent_t evCsr[4] = {};
    if (!s2) {
        cudaStreamCreateWithFlags(&s2, cudaStreamNonBlocking);
        cudaEventCreateWithFlags(&evFork, cudaEventDisableTiming);
        for (int i = 0; i < 4; i++) cudaEventCreateWithFlags(&evCsr[i], cudaEventDisableTiming);
    }

    // ---- fork: per-layer CSR chains on side stream, event per layer ----
    cudaEventRecord(evFork, 0);
    cudaStreamWaitEvent(s2, evFork, 0);

    int scanBlocks = (N_NODES + 1023) / 1024;   // 98
    int srcBase = 0;
    for (int l = 0; l < 4; l++) {
        int lbase = l * N_NODES;
        int E = Es[l];
        init_deg_layer<<<(N_NODES + 255) / 256, 256, 0, s2>>>(lbase);
        hist_layer<<<(E + 255) / 256, 256, 0, s2>>>(eis[l], E, lbase);
        scan1_layer<<<scanBlocks, 1024, 0, s2>>>(lbase);
        scan2_kernel<<<1, 512, 0, s2>>>(scanBlocks);
        scan3_layer<<<(N_NODES + 255) / 256, 256, 0, s2>>>(lbase, srcBase);
        scatter_layer<<<(E + 255) / 256, 256, 0, s2>>>(eis[l], E, lbase);
        cudaEventRecord(evCsr[l], s2);
        srcBase += E + N_NODES;
    }

    // ---- main stream: wprep(fused) -> emb(MMA) -> gemm0 ----
    wprep_all_kernel<<<(8 * H * H + H * F_IN + 255) / 256, 256>>>(Wl, Wr, embW);
    emb_mma<<<(N_NODES + 63) / 64, 256, ESM_TOTAL>>>(x, embb, hA, N_NODES);

    dim3 ggrid((N_NODES + 63) / 64, 2);
    float* hin = hA;
    float* hout = hB;

    mma_gemm<<<ggrid, 256, SM_TOTAL>>>(hin, wh, wl, wh + H * H, wl + H * H, xlp, xrp, N_NODES);

    for (int l = 0; l < 4; l++) {
        if (l > 0) {
            mma_gemm<<<ggrid, 256, SM_TOTAL>>>(hin, wh + (2 * l) * H * H, wl + (2 * l) * H * H,
                                               wh + (2 * l + 1) * H * H, wl + (2 * l + 1) * H * H,
                                               xlp, xrp, N_NODES);
        }
        cudaStreamWaitEvent(0, evCsr[l], 0);     // per-layer join, not global
        gat_agg_kernel<<<(N_NODES * 32 + 255) / 256, 256>>>(
            xlp, xrp, att + l * H, bias + l * H, hout, l * N_NODES);
        float* t = hin; hin = hout; hout = t;
    }

    pool1_kernel<<<POOL_BLKS, 128>>>(hin, ground, batch, ng);
    pool2_kernel<<<(NG * H + 255) / 256, 256>>>();
    final_kernel<<<NG, F_OUT>>>(outW, outb, (float*)d_out);
}